// round 1
// baseline (speedup 1.0000x reference)
#include <cuda_runtime.h>
#include <math.h>

#define HIDDEN 1024
#define NH 16
#define HD 64
#define BATCH 2
#define SEQ 2048
#define BT (BATCH*SEQ)   // 4096

// Scratch (allocation-free rule: __device__ globals)
__device__ float g_q[BATCH*NH*SEQ*HD];      // 16 MB, [b,h,t,d]
__device__ float g_k[BATCH*NH*SEQ*HD];      // 16 MB
__device__ float g_v[BATCH*NH*SEQ*HD];      // 16 MB
__device__ float g_att[BATCH*SEQ*HIDDEN];   // 16 MB, [b,t,h*64+d]

// ---------------------------------------------------------------------------
// Kernel 1: QKV = x @ Wqkv^T + b, fused RoPE, scatter to q/k/v [B,H,T,D]
// Tiles: BM=64, BN=64, BK=16; 256 threads; 4x4 micro-tile per thread.
// BN=64 == one head: blockIdx.y -> (which, head) cleanly.
// ---------------------------------------------------------------------------
__global__ void __launch_bounds__(256) qkv_rope_kernel(
    const float* __restrict__ x, const float* __restrict__ W,
    const float* __restrict__ bias)
{
    __shared__ float sa[16][68];   // [k][m] transposed, padded
    __shared__ float sb[16][68];   // [k][n] transposed, padded

    int tid = threadIdx.x;
    int tx = tid & 15, ty = tid >> 4;
    int m0 = blockIdx.x * 64;
    int n0 = blockIdx.y * 64;
    int lr = tid >> 2;          // 0..63 load row
    int lk = (tid & 3) << 2;    // 0,4,8,12 load k-offset

    float acc[4][4];
    #pragma unroll
    for (int i = 0; i < 4; i++)
        #pragma unroll
        for (int j = 0; j < 4; j++) acc[i][j] = 0.f;

    const float* xp = x + (size_t)(m0 + lr) * HIDDEN + lk;
    const float* wp = W + (size_t)(n0 + lr) * HIDDEN + lk;

    for (int k0 = 0; k0 < HIDDEN; k0 += 16) {
        float4 av = *(const float4*)(xp + k0);
        float4 bv = *(const float4*)(wp + k0);
        __syncthreads();
        sa[lk+0][lr] = av.x; sa[lk+1][lr] = av.y; sa[lk+2][lr] = av.z; sa[lk+3][lr] = av.w;
        sb[lk+0][lr] = bv.x; sb[lk+1][lr] = bv.y; sb[lk+2][lr] = bv.z; sb[lk+3][lr] = bv.w;
        __syncthreads();
        #pragma unroll
        for (int kk = 0; kk < 16; kk++) {
            float4 a = *(const float4*)&sa[kk][ty << 2];
            float4 b = *(const float4*)&sb[kk][tx << 2];
            float ar[4] = {a.x, a.y, a.z, a.w};
            float br[4] = {b.x, b.y, b.z, b.w};
            #pragma unroll
            for (int i = 0; i < 4; i++)
                #pragma unroll
                for (int j = 0; j < 4; j++)
                    acc[i][j] += ar[i] * br[j];
        }
    }

    int which = blockIdx.y >> 4;       // 0=q,1=k,2=v
    int h = blockIdx.y & 15;
    int d0 = tx << 2;
    float b0 = bias[n0+d0+0], b1 = bias[n0+d0+1], b2 = bias[n0+d0+2], b3 = bias[n0+d0+3];

    // RoPE pair indices for this thread's 4 cols: pairs (d0,d0+1)->p0, (d0+2,d0+3)->p1
    int p0 = d0 >> 1;
    int p1 = p0 + 1;
    const float LG10000 = 13.2877123795494f;   // log2(10000)
    float invf0 = exp2f(-((float)p0 * (1.0f/32.0f)) * LG10000);
    float invf1 = exp2f(-((float)p1 * (1.0f/32.0f)) * LG10000);

    #pragma unroll
    for (int i = 0; i < 4; i++) {
        int m = m0 + (ty << 2) + i;
        int bb = m >> 11;
        int t  = m & 2047;
        float v0 = acc[i][0] + b0, v1 = acc[i][1] + b1;
        float v2 = acc[i][2] + b2, v3 = acc[i][3] + b3;
        size_t base = ((size_t)(bb * NH + h) * SEQ + t) * HD + d0;
        if (which == 2) {
            g_v[base+0] = v0; g_v[base+1] = v1; g_v[base+2] = v2; g_v[base+3] = v3;
        } else {
            float s0, c0, s1, c1;
            sincosf((float)t * invf0, &s0, &c0);
            sincosf((float)t * invf1, &s1, &c1);
            float r0 = v0 * c0 - v1 * s0;
            float r1 = v0 * s0 + v1 * c0;
            float r2 = v2 * c1 - v3 * s1;
            float r3 = v2 * s1 + v3 * c1;
            float* dst = (which == 0) ? g_q : g_k;
            dst[base+0] = r0; dst[base+1] = r1; dst[base+2] = r2; dst[base+3] = r3;
        }
    }
}

// ---------------------------------------------------------------------------
// Kernel 2: causal flash attention, fp32. 64-row q-tile per block, 256 threads.
// Warp w owns rows w*8..w*8+7 -> softmax stats are warp-local shuffles.
// Lane l owns cols/dims 2l, 2l+1.
// Output written directly in [B,T,H*D] layout for the out-projection GEMM.
// Global-token branch of the reference is a provable no-op (identical mask) -> skipped.
// ---------------------------------------------------------------------------
#define ATTN_SMEM (4 * 64 * 68 * 4)

__global__ void __launch_bounds__(256) attn_kernel()
{
    extern __shared__ float sm[];
    float* sq  = sm;                 // [r][d]  64x68
    float* skt = sq  + 64 * 68;      // [d][c]  64x68 (K transposed)
    float* sv  = skt + 64 * 68;      // [c][d]  64x68
    float* sp  = sv  + 64 * 68;      // [r][c]  64x68

    int tid  = threadIdx.x;
    int lane = tid & 31;
    int warp = tid >> 5;
    int qt = blockIdx.x;             // q-tile (0..31)
    int bh = blockIdx.y;             // b*16+h (0..31)

    const float* qp = g_q + ((size_t)bh * SEQ + (size_t)qt * 64) * HD;
    const float* kp = g_k + (size_t)bh * SEQ * HD;
    const float* vp = g_v + (size_t)bh * SEQ * HD;

    // Load Q tile
    #pragma unroll
    for (int it = 0; it < 4; it++) {
        int idx = tid + it * 256;           // float4 index 0..1023
        int r = idx >> 4;
        int c = (idx & 15) << 2;
        float4 v = *(const float4*)&qp[r * HD + c];
        *(float4*)&sq[r * 68 + c] = v;
    }

    float m_i[8], l_i[8], o0[8], o1[8];
    #pragma unroll
    for (int i = 0; i < 8; i++) { m_i[i] = -3.0e38f; l_i[i] = 0.f; o0[i] = 0.f; o1[i] = 0.f; }
    int r_base = warp * 8;
    const float scale = 0.125f;   // 1/sqrt(64)

    for (int kt = 0; kt <= qt; kt++) {
        __syncthreads();   // previous tile fully consumed
        // Load K (transposed) and V tiles
        #pragma unroll
        for (int it = 0; it < 4; it++) {
            int idx = tid + it * 256;
            int r = idx >> 4;
            int c = (idx & 15) << 2;
            float4 kv = *(const float4*)&kp[((size_t)kt * 64 + r) * HD + c];
            skt[(c+0)*68 + r] = kv.x; skt[(c+1)*68 + r] = kv.y;
            skt[(c+2)*68 + r] = kv.z; skt[(c+3)*68 + r] = kv.w;
            float4 vv = *(const float4*)&vp[((size_t)kt * 64 + r) * HD + c];
            *(float4*)&sv[r * 68 + c] = vv;
        }
        __syncthreads();

        // S = Q K^T (each lane: 8 rows x 2 cols)
        float s0[8], s1[8];
        #pragma unroll
        for (int i = 0; i < 8; i++) { s0[i] = 0.f; s1[i] = 0.f; }
        #pragma unroll 8
        for (int d = 0; d < 64; d++) {
            float2 kvv = *(const float2*)&skt[d * 68 + (lane << 1)];
            #pragma unroll
            for (int i = 0; i < 8; i++) {
                float qv = sq[(r_base + i) * 68 + d];
                s0[i] += qv * kvv.x;
                s1[i] += qv * kvv.y;
            }
        }

        bool diag = (kt == qt);
        int c0 = kt * 64 + (lane << 1);
        int c1 = c0 + 1;
        #pragma unroll
        for (int i = 0; i < 8; i++) {
            int rg = qt * 64 + r_base + i;
            float x0 = s0[i] * scale;
            float x1 = s1[i] * scale;
            if (diag) {
                if (c0 > rg) x0 = -1.0e9f;
                if (c1 > rg) x1 = -1.0e9f;
            }
            float mx = fmaxf(x0, x1);
            #pragma unroll
            for (int off = 16; off > 0; off >>= 1)
                mx = fmaxf(mx, __shfl_xor_sync(0xffffffffu, mx, off));
            float mnew = fmaxf(m_i[i], mx);
            float p0 = __expf(x0 - mnew);
            float p1 = __expf(x1 - mnew);
            float rs = p0 + p1;
            #pragma unroll
            for (int off = 16; off > 0; off >>= 1)
                rs += __shfl_xor_sync(0xffffffffu, rs, off);
            float alpha = __expf(m_i[i] - mnew);
            l_i[i] = l_i[i] * alpha + rs;
            m_i[i] = mnew;
            o0[i] *= alpha;
            o1[i] *= alpha;
            *(float2*)&sp[(r_base + i) * 68 + (lane << 1)] = make_float2(p0, p1);
        }
        __syncwarp();   // P rows are warp-private: warp sync is enough

        // O += P V
        #pragma unroll 8
        for (int c = 0; c < 64; c++) {
            float2 vv = *(const float2*)&sv[c * 68 + (lane << 1)];
            #pragma unroll
            for (int i = 0; i < 8; i++) {
                float pv = sp[(r_base + i) * 68 + c];
                o0[i] += pv * vv.x;
                o1[i] += pv * vv.y;
            }
        }
    }

    // Epilogue: normalize, write [B,T,H*D]
    int b = bh >> 4;
    int h = bh & 15;
    #pragma unroll
    for (int i = 0; i < 8; i++) {
        float inv = 1.0f / l_i[i];
        int t = qt * 64 + r_base + i;
        size_t base = ((size_t)b * SEQ + t) * HIDDEN + h * HD + (lane << 1);
        *(float2*)&g_att[base] = make_float2(o0[i] * inv, o1[i] * inv);
    }
}

// ---------------------------------------------------------------------------
// Kernel 3: out = att @ Wout^T + bout  (4096 x 1024 x 1024)
// ---------------------------------------------------------------------------
__global__ void __launch_bounds__(256) out_proj_kernel(
    const float* __restrict__ W, const float* __restrict__ bias,
    float* __restrict__ out)
{
    __shared__ float sa[16][68];
    __shared__ float sb[16][68];

    int tid = threadIdx.x;
    int tx = tid & 15, ty = tid >> 4;
    int m0 = blockIdx.x * 64;
    int n0 = blockIdx.y * 64;
    int lr = tid >> 2;
    int lk = (tid & 3) << 2;

    float acc[4][4];
    #pragma unroll
    for (int i = 0; i < 4; i++)
        #pragma unroll
        for (int j = 0; j < 4; j++) acc[i][j] = 0.f;

    const float* xp = g_att + (size_t)(m0 + lr) * HIDDEN + lk;
    const float* wp = W + (size_t)(n0 + lr) * HIDDEN + lk;

    for (int k0 = 0; k0 < HIDDEN; k0 += 16) {
        float4 av = *(const float4*)(xp + k0);
        float4 bv = *(const float4*)(wp + k0);
        __syncthreads();
        sa[lk+0][lr] = av.x; sa[lk+1][lr] = av.y; sa[lk+2][lr] = av.z; sa[lk+3][lr] = av.w;
        sb[lk+0][lr] = bv.x; sb[lk+1][lr] = bv.y; sb[lk+2][lr] = bv.z; sb[lk+3][lr] = bv.w;
        __syncthreads();
        #pragma unroll
        for (int kk = 0; kk < 16; kk++) {
            float4 a = *(const float4*)&sa[kk][ty << 2];
            float4 b = *(const float4*)&sb[kk][tx << 2];
            float ar[4] = {a.x, a.y, a.z, a.w};
            float br[4] = {b.x, b.y, b.z, b.w};
            #pragma unroll
            for (int i = 0; i < 4; i++)
                #pragma unroll
                for (int j = 0; j < 4; j++)
                    acc[i][j] += ar[i] * br[j];
        }
    }

    #pragma unroll
    for (int i = 0; i < 4; i++) {
        int m = m0 + (ty << 2) + i;
        #pragma unroll
        for (int j = 0; j < 4; j++) {
            int n = n0 + (tx << 2) + j;
            out[(size_t)m * HIDDEN + n] = acc[i][j] + bias[n];
        }
    }
}

// ---------------------------------------------------------------------------
extern "C" void kernel_launch(void* const* d_in, const int* in_sizes, int n_in,
                              void* d_out, int out_size)
{
    const float* x    = (const float*)d_in[0];
    // d_in[1] = mask (bool) — pure causal, unused
    const float* Wqkv = (const float*)d_in[2];
    const float* bqkv = (const float*)d_in[3];
    const float* Wout = (const float*)d_in[4];
    const float* bout = (const float*)d_in[5];
    float* out = (float*)d_out;

    qkv_rope_kernel<<<dim3(BT/64, 3*HIDDEN/64), 256>>>(x, Wqkv, bqkv);

    cudaFuncSetAttribute(attn_kernel, cudaFuncAttributeMaxDynamicSharedMemorySize, ATTN_SMEM);
    attn_kernel<<<dim3(SEQ/64, BATCH*NH), 256, ATTN_SMEM>>>();

    out_proj_kernel<<<dim3(BT/64, HIDDEN/64), 256>>>(Wout, bout, out);
}

// round 3
// speedup vs baseline: 1.6500x; 1.6500x over previous
#include <cuda_runtime.h>
#include <cuda_bf16.h>
#include <math.h>
#include <stdint.h>

#define HIDDEN 1024
#define NH 16
#define HD 64
#define BATCH 2
#define SEQ 2048
#define BT (BATCH*SEQ)   // 4096

// Scratch (allocation-free rule: __device__ globals)
__device__ float g_q[BATCH*NH*SEQ*HD];      // [b,h,t,d]
__device__ float g_k[BATCH*NH*SEQ*HD];
__device__ float g_v[BATCH*NH*SEQ*HD];
__device__ float g_att[BATCH*SEQ*HIDDEN];   // [b,t,h*64+d]

// ===========================================================================
// Warp-level tensor-core primitives (baseline sm_103 target: mma.sync/ldmatrix)
// ===========================================================================
__device__ __forceinline__ uint32_t smem_to_u32(const void* smem_ptr) {
    uint32_t addr;
    asm("{ .reg .u64 tmp; cvta.to.shared.u64 tmp, %1; cvt.u32.u64 %0, tmp; }"
        : "=r"(addr) : "l"(smem_ptr));
    return addr;
}

__device__ __forceinline__ void ldsm_x4(uint32_t& r0, uint32_t& r1,
                                        uint32_t& r2, uint32_t& r3, uint32_t addr) {
    asm volatile("ldmatrix.sync.aligned.m8n8.x4.shared.b16 {%0,%1,%2,%3}, [%4];"
                 : "=r"(r0), "=r"(r1), "=r"(r2), "=r"(r3) : "r"(addr));
}

__device__ __forceinline__ void mma_bf16(float& c0, float& c1, float& c2, float& c3,
                                         uint32_t a0, uint32_t a1, uint32_t a2, uint32_t a3,
                                         uint32_t b0, uint32_t b1) {
    asm volatile(
        "mma.sync.aligned.m16n8k16.row.col.f32.bf16.bf16.f32 "
        "{%0,%1,%2,%3}, {%4,%5,%6,%7}, {%8,%9}, {%0,%1,%2,%3};"
        : "+f"(c0), "+f"(c1), "+f"(c2), "+f"(c3)
        : "r"(a0), "r"(a1), "r"(a2), "r"(a3), "r"(b0), "r"(b1));
}

// ===========================================================================
// HMMA GEMM: C[M=4096, N] = X[M,1024] @ W[N,1024]^T (+bias, +epilogue)
// CTA tile 128x128, 8 warps (2 M x 4 N), warp tile 64x32.
// bf16 two-term split (hi/lo): C = Ah*Bh + Ah*Bl + Al*Bh (fp32 accum).
// SMEM: 4 tiles [128][72] bf16 (Ah, Al, Bh, Bl); stride 72 -> LDSM conflict-free.
// MODE 0: QKV + bias + RoPE -> g_q/g_k/g_v ; MODE 1: X=g_att, +bias -> out
// ===========================================================================
#define GSTRIDE 72
#define GTILE   (128 * GSTRIDE)           // bf16 elements per tile
#define GEMM_SMEM (4 * GTILE * 2)         // 73728 bytes

template<int MODE>
__global__ void __launch_bounds__(256) gemm_tc_kernel(
    const float* __restrict__ Xin, const float* __restrict__ W,
    const float* __restrict__ bias, float* __restrict__ out)
{
    extern __shared__ __nv_bfloat16 sm[];
    __nv_bfloat16* sAh = sm;
    __nv_bfloat16* sAl = sm + GTILE;
    __nv_bfloat16* sBh = sm + 2 * GTILE;
    __nv_bfloat16* sBl = sm + 3 * GTILE;
    const uint32_t sAh_u = smem_to_u32(sAh);
    const uint32_t sAl_u = sAh_u + GTILE * 2;
    const uint32_t sBh_u = sAh_u + 2 * GTILE * 2;
    const uint32_t sBl_u = sAh_u + 3 * GTILE * 2;

    const float* X = (MODE == 1) ? g_att : Xin;

    int tid = threadIdx.x;
    int lane = tid & 31;
    int wid = tid >> 5;
    int warpM = (wid & 1) << 6;     // 0 or 64
    int warpN = (wid >> 1) << 5;    // 0,32,64,96
    int m0 = blockIdx.x * 128;
    int n0 = blockIdx.y * 128;

    // Per-lane ldmatrix address offsets (in bf16 elements, before *2 for bytes)
    int a_row = lane & 15;
    int a_kof = (lane >> 4) << 3;               // 0 or 8
    int b_g = lane >> 3, b_i = lane & 7;
    int b_nof = (b_g >> 1) << 3;                // 0 or 8
    int b_kof = (b_g & 1) << 3;                 // 0 or 8

    // Load staging indices: thread handles 8 float4 loads per operand per chunk
    int l_row = tid >> 4;                       // 0..15 (+16 per iter)
    int l_kc  = (tid & 15) << 2;                // 0..60

    float c[4][4][4];
    #pragma unroll
    for (int mt = 0; mt < 4; mt++)
        #pragma unroll
        for (int nt = 0; nt < 4; nt++)
            #pragma unroll
            for (int r = 0; r < 4; r++) c[mt][nt][r] = 0.f;

    for (int ch = 0; ch < 16; ch++) {
        int k0 = ch << 6;
        if (ch) __syncthreads();   // all warps done reading previous chunk
        // Stage A (X) and B (W) with hi/lo split
        #pragma unroll
        for (int i = 0; i < 8; i++) {
            int row = l_row + (i << 4);
            float4 v = *(const float4*)&X[(size_t)(m0 + row) * HIDDEN + k0 + l_kc];
            __nv_bfloat162 h01 = __floats2bfloat162_rn(v.x, v.y);
            __nv_bfloat162 h23 = __floats2bfloat162_rn(v.z, v.w);
            float2 f01 = __bfloat1622float2(h01);
            float2 f23 = __bfloat1622float2(h23);
            __nv_bfloat162 l01 = __floats2bfloat162_rn(v.x - f01.x, v.y - f01.y);
            __nv_bfloat162 l23 = __floats2bfloat162_rn(v.z - f23.x, v.w - f23.y);
            int off = row * GSTRIDE + l_kc;
            *(uint2*)&sAh[off] = make_uint2(*(uint32_t*)&h01, *(uint32_t*)&h23);
            *(uint2*)&sAl[off] = make_uint2(*(uint32_t*)&l01, *(uint32_t*)&l23);
        }
        #pragma unroll
        for (int i = 0; i < 8; i++) {
            int row = l_row + (i << 4);
            float4 v = *(const float4*)&W[(size_t)(n0 + row) * HIDDEN + k0 + l_kc];
            __nv_bfloat162 h01 = __floats2bfloat162_rn(v.x, v.y);
            __nv_bfloat162 h23 = __floats2bfloat162_rn(v.z, v.w);
            float2 f01 = __bfloat1622float2(h01);
            float2 f23 = __bfloat1622float2(h23);
            __nv_bfloat162 l01 = __floats2bfloat162_rn(v.x - f01.x, v.y - f01.y);
            __nv_bfloat162 l23 = __floats2bfloat162_rn(v.z - f23.x, v.w - f23.y);
            int off = row * GSTRIDE + l_kc;
            *(uint2*)&sBh[off] = make_uint2(*(uint32_t*)&h01, *(uint32_t*)&h23);
            *(uint2*)&sBl[off] = make_uint2(*(uint32_t*)&l01, *(uint32_t*)&l23);
        }
        __syncthreads();

        #pragma unroll
        for (int k16 = 0; k16 < 4; k16++) {
            int kk = k16 << 4;
            uint32_t ah[4][4], al[4][4], bh[4][2], bl[4][2];
            #pragma unroll
            for (int mt = 0; mt < 4; mt++) {
                uint32_t off = ((warpM + (mt << 4) + a_row) * GSTRIDE + kk + a_kof) * 2;
                ldsm_x4(ah[mt][0], ah[mt][1], ah[mt][2], ah[mt][3], sAh_u + off);
                ldsm_x4(al[mt][0], al[mt][1], al[mt][2], al[mt][3], sAl_u + off);
            }
            #pragma unroll
            for (int np = 0; np < 2; np++) {
                uint32_t off = ((warpN + (np << 4) + b_nof + b_i) * GSTRIDE + kk + b_kof) * 2;
                ldsm_x4(bh[2*np][0], bh[2*np][1], bh[2*np+1][0], bh[2*np+1][1], sBh_u + off);
                ldsm_x4(bl[2*np][0], bl[2*np][1], bl[2*np+1][0], bl[2*np+1][1], sBl_u + off);
            }
            #pragma unroll
            for (int mt = 0; mt < 4; mt++)
                #pragma unroll
                for (int nt = 0; nt < 4; nt++) {
                    mma_bf16(c[mt][nt][0], c[mt][nt][1], c[mt][nt][2], c[mt][nt][3],
                             ah[mt][0], ah[mt][1], ah[mt][2], ah[mt][3],
                             bh[nt][0], bh[nt][1]);
                    mma_bf16(c[mt][nt][0], c[mt][nt][1], c[mt][nt][2], c[mt][nt][3],
                             ah[mt][0], ah[mt][1], ah[mt][2], ah[mt][3],
                             bl[nt][0], bl[nt][1]);
                    mma_bf16(c[mt][nt][0], c[mt][nt][1], c[mt][nt][2], c[mt][nt][3],
                             al[mt][0], al[mt][1], al[mt][2], al[mt][3],
                             bh[nt][0], bh[nt][1]);
                }
        }
    }

    // ------------------- Epilogue from C fragments -------------------
    // frag (mt,nt): regs {0,1} -> row = warpM+mt*16+(lane>>2),   cols col,col+1
    //               regs {2,3} -> row += 8
    // col = n0 + warpN + nt*8 + (lane&3)*2  (adjacent even/odd = RoPE pair)
    int quad = lane >> 2, qi = lane & 3;
    const float LG10000 = 13.2877123795494f;   // log2(10000)

    #pragma unroll
    for (int nt = 0; nt < 4; nt++) {
        int col = n0 + warpN + (nt << 3) + (qi << 1);
        float b0 = bias[col], b1 = bias[col + 1];
        if (MODE == 1) {
            #pragma unroll
            for (int mt = 0; mt < 4; mt++) {
                int r0 = m0 + warpM + (mt << 4) + quad;
                *(float2*)&out[(size_t)r0 * HIDDEN + col] =
                    make_float2(c[mt][nt][0] + b0, c[mt][nt][1] + b1);
                *(float2*)&out[(size_t)(r0 + 8) * HIDDEN + col] =
                    make_float2(c[mt][nt][2] + b0, c[mt][nt][3] + b1);
            }
        } else {
            int which = col >> 10;
            int h = (col >> 6) & 15;
            int d = col & 63;
            size_t hb = (size_t)h * SEQ * HD;
            if (which == 2) {
                #pragma unroll
                for (int mt = 0; mt < 4; mt++) {
                    int r0 = m0 + warpM + (mt << 4) + quad;
                    #pragma unroll
                    for (int rr = 0; rr < 2; rr++) {
                        int m = r0 + (rr << 3);
                        int bb = m >> 11, t = m & 2047;
                        size_t base = ((size_t)bb * NH) * SEQ * HD + hb + (size_t)t * HD + d;
                        *(float2*)&g_v[base] =
                            make_float2(c[mt][nt][2*rr] + b0, c[mt][nt][2*rr+1] + b1);
                    }
                }
            } else {
                float* dst = which ? g_k : g_q;
                int p = d >> 1;
                float invf = exp2f(-((float)p * (1.0f / 32.0f)) * LG10000);
                #pragma unroll
                for (int mt = 0; mt < 4; mt++) {
                    int r0 = m0 + warpM + (mt << 4) + quad;
                    #pragma unroll
                    for (int rr = 0; rr < 2; rr++) {
                        int m = r0 + (rr << 3);
                        int bb = m >> 11, t = m & 2047;
                        float s, cc;
                        sincosf((float)t * invf, &s, &cc);
                        float x1 = c[mt][nt][2*rr] + b0;
                        float x2 = c[mt][nt][2*rr+1] + b1;
                        size_t base = ((size_t)bb * NH) * SEQ * HD + hb + (size_t)t * HD + d;
                        *(float2*)&dst[base] =
                            make_float2(x1 * cc - x2 * s, x1 * s + x2 * cc);
                    }
                }
            }
        }
    }
}

// ---------------------------------------------------------------------------
// Kernel 2: causal flash attention, fp32 (unchanged from R1 — passed).
// ---------------------------------------------------------------------------
#define ATTN_SMEM (4 * 64 * 68 * 4)

__global__ void __launch_bounds__(256) attn_kernel()
{
    extern __shared__ float smf[];
    float* sq  = smf;
    float* skt = sq  + 64 * 68;
    float* sv  = skt + 64 * 68;
    float* sp  = sv  + 64 * 68;

    int tid  = threadIdx.x;
    int lane = tid & 31;
    int warp = tid >> 5;
    int qt = blockIdx.x;
    int bh = blockIdx.y;

    const float* qp = g_q + ((size_t)bh * SEQ + (size_t)qt * 64) * HD;
    const float* kp = g_k + (size_t)bh * SEQ * HD;
    const float* vp = g_v + (size_t)bh * SEQ * HD;

    #pragma unroll
    for (int it = 0; it < 4; it++) {
        int idx = tid + it * 256;
        int r = idx >> 4;
        int c = (idx & 15) << 2;
        float4 v = *(const float4*)&qp[r * HD + c];
        *(float4*)&sq[r * 68 + c] = v;
    }

    float m_i[8], l_i[8], o0[8], o1[8];
    #pragma unroll
    for (int i = 0; i < 8; i++) { m_i[i] = -3.0e38f; l_i[i] = 0.f; o0[i] = 0.f; o1[i] = 0.f; }
    int r_base = warp * 8;
    const float scale = 0.125f;

    for (int kt = 0; kt <= qt; kt++) {
        __syncthreads();
        #pragma unroll
        for (int it = 0; it < 4; it++) {
            int idx = tid + it * 256;
            int r = idx >> 4;
            int c = (idx & 15) << 2;
            float4 kv = *(const float4*)&kp[((size_t)kt * 64 + r) * HD + c];
            skt[(c+0)*68 + r] = kv.x; skt[(c+1)*68 + r] = kv.y;
            skt[(c+2)*68 + r] = kv.z; skt[(c+3)*68 + r] = kv.w;
            float4 vv = *(const float4*)&vp[((size_t)kt * 64 + r) * HD + c];
            *(float4*)&sv[r * 68 + c] = vv;
        }
        __syncthreads();

        float s0[8], s1[8];
        #pragma unroll
        for (int i = 0; i < 8; i++) { s0[i] = 0.f; s1[i] = 0.f; }
        #pragma unroll 8
        for (int d = 0; d < 64; d++) {
            float2 kvv = *(const float2*)&skt[d * 68 + (lane << 1)];
            #pragma unroll
            for (int i = 0; i < 8; i++) {
                float qv = sq[(r_base + i) * 68 + d];
                s0[i] += qv * kvv.x;
                s1[i] += qv * kvv.y;
            }
        }

        bool diag = (kt == qt);
        int c0 = kt * 64 + (lane << 1);
        int c1 = c0 + 1;
        #pragma unroll
        for (int i = 0; i < 8; i++) {
            int rg = qt * 64 + r_base + i;
            float x0 = s0[i] * scale;
            float x1 = s1[i] * scale;
            if (diag) {
                if (c0 > rg) x0 = -1.0e9f;
                if (c1 > rg) x1 = -1.0e9f;
            }
            float mx = fmaxf(x0, x1);
            #pragma unroll
            for (int off = 16; off > 0; off >>= 1)
                mx = fmaxf(mx, __shfl_xor_sync(0xffffffffu, mx, off));
            float mnew = fmaxf(m_i[i], mx);
            float p0 = __expf(x0 - mnew);
            float p1 = __expf(x1 - mnew);
            float rs = p0 + p1;
            #pragma unroll
            for (int off = 16; off > 0; off >>= 1)
                rs += __shfl_xor_sync(0xffffffffu, rs, off);
            float alpha = __expf(m_i[i] - mnew);
            l_i[i] = l_i[i] * alpha + rs;
            m_i[i] = mnew;
            o0[i] *= alpha;
            o1[i] *= alpha;
            *(float2*)&sp[(r_base + i) * 68 + (lane << 1)] = make_float2(p0, p1);
        }
        __syncwarp();

        #pragma unroll 8
        for (int c = 0; c < 64; c++) {
            float2 vv = *(const float2*)&sv[c * 68 + (lane << 1)];
            #pragma unroll
            for (int i = 0; i < 8; i++) {
                float pv = sp[(r_base + i) * 68 + c];
                o0[i] += pv * vv.x;
                o1[i] += pv * vv.y;
            }
        }
    }

    int b = bh >> 4;
    int h = bh & 15;
    #pragma unroll
    for (int i = 0; i < 8; i++) {
        float inv = 1.0f / l_i[i];
        int t = qt * 64 + r_base + i;
        size_t base = ((size_t)b * SEQ + t) * HIDDEN + h * HD + (lane << 1);
        *(float2*)&g_att[base] = make_float2(o0[i] * inv, o1[i] * inv);
    }
}

// ---------------------------------------------------------------------------
extern "C" void kernel_launch(void* const* d_in, const int* in_sizes, int n_in,
                              void* d_out, int out_size)
{
    const float* x    = (const float*)d_in[0];
    // d_in[1] = mask (bool) — pure causal, unused
    const float* Wqkv = (const float*)d_in[2];
    const float* bqkv = (const float*)d_in[3];
    const float* Wout = (const float*)d_in[4];
    const float* bout = (const float*)d_in[5];
    float* out = (float*)d_out;

    cudaFuncSetAttribute(gemm_tc_kernel<0>, cudaFuncAttributeMaxDynamicSharedMemorySize, GEMM_SMEM);
    cudaFuncSetAttribute(gemm_tc_kernel<1>, cudaFuncAttributeMaxDynamicSharedMemorySize, GEMM_SMEM);
    cudaFuncSetAttribute(attn_kernel, cudaFuncAttributeMaxDynamicSharedMemorySize, ATTN_SMEM);

    // QKV + RoPE: M=4096, N=3072
    gemm_tc_kernel<0><<<dim3(BT/128, 3*HIDDEN/128), 256, GEMM_SMEM>>>(x, Wqkv, bqkv, nullptr);

    // Flash attention (fp32)
    attn_kernel<<<dim3(SEQ/64, BATCH*NH), 256, ATTN_SMEM>>>();

    // Out projection: M=4096, N=1024 (reads g_att internally)
    gemm_tc_kernel<1><<<dim3(BT/128, HIDDEN/128), 256, GEMM_SMEM>>>(nullptr, Wout, bout, out);
}

// round 4
// speedup vs baseline: 3.0916x; 1.8737x over previous
#include <cuda_runtime.h>
#include <cuda_bf16.h>
#include <math.h>
#include <stdint.h>

#define HIDDEN 1024
#define NH 16
#define HD 64
#define BATCH 2
#define SEQ 2048
#define BT (BATCH*SEQ)   // 4096

// Scratch (allocation-free rule: __device__ globals)
// Q/K/V as bf16 two-term splits, [b,h,t,d]; Q pre-scaled by 1/8.
__device__ __nv_bfloat16 g_qh[BATCH*NH*SEQ*HD];
__device__ __nv_bfloat16 g_ql[BATCH*NH*SEQ*HD];
__device__ __nv_bfloat16 g_kh[BATCH*NH*SEQ*HD];
__device__ __nv_bfloat16 g_kl[BATCH*NH*SEQ*HD];
__device__ __nv_bfloat16 g_vh[BATCH*NH*SEQ*HD];
__device__ __nv_bfloat16 g_vl[BATCH*NH*SEQ*HD];
__device__ float g_att[BATCH*SEQ*HIDDEN];   // [b,t,h*64+d]

// ===========================================================================
// Warp-level tensor-core primitives
// ===========================================================================
__device__ __forceinline__ uint32_t smem_to_u32(const void* smem_ptr) {
    uint32_t addr;
    asm("{ .reg .u64 tmp; cvta.to.shared.u64 tmp, %1; cvt.u32.u64 %0, tmp; }"
        : "=r"(addr) : "l"(smem_ptr));
    return addr;
}

__device__ __forceinline__ void ldsm_x4(uint32_t& r0, uint32_t& r1,
                                        uint32_t& r2, uint32_t& r3, uint32_t addr) {
    asm volatile("ldmatrix.sync.aligned.m8n8.x4.shared.b16 {%0,%1,%2,%3}, [%4];"
                 : "=r"(r0), "=r"(r1), "=r"(r2), "=r"(r3) : "r"(addr));
}
__device__ __forceinline__ void ldsm_x4_t(uint32_t& r0, uint32_t& r1,
                                          uint32_t& r2, uint32_t& r3, uint32_t addr) {
    asm volatile("ldmatrix.sync.aligned.m8n8.x4.trans.shared.b16 {%0,%1,%2,%3}, [%4];"
                 : "=r"(r0), "=r"(r1), "=r"(r2), "=r"(r3) : "r"(addr));
}

__device__ __forceinline__ void mma_bf16(float* c,
                                         uint32_t a0, uint32_t a1, uint32_t a2, uint32_t a3,
                                         uint32_t b0, uint32_t b1) {
    asm volatile(
        "mma.sync.aligned.m16n8k16.row.col.f32.bf16.bf16.f32 "
        "{%0,%1,%2,%3}, {%4,%5,%6,%7}, {%8,%9}, {%0,%1,%2,%3};"
        : "+f"(c[0]), "+f"(c[1]), "+f"(c[2]), "+f"(c[3])
        : "r"(a0), "r"(a1), "r"(a2), "r"(a3), "r"(b0), "r"(b1));
}

__device__ __forceinline__ void split_pair(float x1, float x2, uint32_t& h, uint32_t& l) {
    __nv_bfloat162 hh = __floats2bfloat162_rn(x1, x2);
    float2 hf = __bfloat1622float2(hh);
    __nv_bfloat162 ll = __floats2bfloat162_rn(x1 - hf.x, x2 - hf.y);
    h = *reinterpret_cast<uint32_t*>(&hh);
    l = *reinterpret_cast<uint32_t*>(&ll);
}

// ===========================================================================
// HMMA GEMM: C[M=4096, N] = X[M,1024] @ W[N,1024]^T (+bias, +epilogue)
// CTA tile 128x128, 8 warps (2 M x 4 N), warp tile 64x32; bf16 hi/lo split.
// MODE 0: QKV + bias + RoPE -> bf16-split g_q*/g_k*/g_v* ; MODE 1: -> out fp32
// ===========================================================================
#define GSTRIDE 72
#define GTILE   (128 * GSTRIDE)
#define GEMM_SMEM (4 * GTILE * 2)         // 73728 bytes

template<int MODE>
__global__ void __launch_bounds__(256) gemm_tc_kernel(
    const float* __restrict__ Xin, const float* __restrict__ W,
    const float* __restrict__ bias, float* __restrict__ out)
{
    extern __shared__ __nv_bfloat16 sm[];
    __nv_bfloat16* sAh = sm;
    __nv_bfloat16* sAl = sm + GTILE;
    __nv_bfloat16* sBh = sm + 2 * GTILE;
    __nv_bfloat16* sBl = sm + 3 * GTILE;
    const uint32_t sAh_u = smem_to_u32(sAh);
    const uint32_t sAl_u = sAh_u + GTILE * 2;
    const uint32_t sBh_u = sAh_u + 2 * GTILE * 2;
    const uint32_t sBl_u = sAh_u + 3 * GTILE * 2;

    const float* X = (MODE == 1) ? g_att : Xin;

    int tid = threadIdx.x;
    int lane = tid & 31;
    int wid = tid >> 5;
    int warpM = (wid & 1) << 6;
    int warpN = (wid >> 1) << 5;
    int m0 = blockIdx.x * 128;
    int n0 = blockIdx.y * 128;

    int a_row = lane & 15;
    int a_kof = (lane >> 4) << 3;
    int b_g = lane >> 3, b_i = lane & 7;
    int b_nof = (b_g >> 1) << 3;
    int b_kof = (b_g & 1) << 3;

    int l_row = tid >> 4;
    int l_kc  = (tid & 15) << 2;

    float c[4][4][4];
    #pragma unroll
    for (int mt = 0; mt < 4; mt++)
        #pragma unroll
        for (int nt = 0; nt < 4; nt++)
            #pragma unroll
            for (int r = 0; r < 4; r++) c[mt][nt][r] = 0.f;

    for (int ch = 0; ch < 16; ch++) {
        int k0 = ch << 6;
        if (ch) __syncthreads();
        #pragma unroll
        for (int i = 0; i < 8; i++) {
            int row = l_row + (i << 4);
            float4 v = *(const float4*)&X[(size_t)(m0 + row) * HIDDEN + k0 + l_kc];
            uint32_t h01, l01, h23, l23;
            split_pair(v.x, v.y, h01, l01);
            split_pair(v.z, v.w, h23, l23);
            int off = row * GSTRIDE + l_kc;
            *(uint2*)&sAh[off] = make_uint2(h01, h23);
            *(uint2*)&sAl[off] = make_uint2(l01, l23);
        }
        #pragma unroll
        for (int i = 0; i < 8; i++) {
            int row = l_row + (i << 4);
            float4 v = *(const float4*)&W[(size_t)(n0 + row) * HIDDEN + k0 + l_kc];
            uint32_t h01, l01, h23, l23;
            split_pair(v.x, v.y, h01, l01);
            split_pair(v.z, v.w, h23, l23);
            int off = row * GSTRIDE + l_kc;
            *(uint2*)&sBh[off] = make_uint2(h01, h23);
            *(uint2*)&sBl[off] = make_uint2(l01, l23);
        }
        __syncthreads();

        #pragma unroll
        for (int k16 = 0; k16 < 4; k16++) {
            int kk = k16 << 4;
            uint32_t ah[4][4], al[4][4], bh[4][2], bl[4][2];
            #pragma unroll
            for (int mt = 0; mt < 4; mt++) {
                uint32_t off = ((warpM + (mt << 4) + a_row) * GSTRIDE + kk + a_kof) * 2;
                ldsm_x4(ah[mt][0], ah[mt][1], ah[mt][2], ah[mt][3], sAh_u + off);
                ldsm_x4(al[mt][0], al[mt][1], al[mt][2], al[mt][3], sAl_u + off);
            }
            #pragma unroll
            for (int np = 0; np < 2; np++) {
                uint32_t off = ((warpN + (np << 4) + b_nof + b_i) * GSTRIDE + kk + b_kof) * 2;
                ldsm_x4(bh[2*np][0], bh[2*np][1], bh[2*np+1][0], bh[2*np+1][1], sBh_u + off);
                ldsm_x4(bl[2*np][0], bl[2*np][1], bl[2*np+1][0], bl[2*np+1][1], sBl_u + off);
            }
            #pragma unroll
            for (int mt = 0; mt < 4; mt++)
                #pragma unroll
                for (int nt = 0; nt < 4; nt++) {
                    mma_bf16(c[mt][nt], ah[mt][0], ah[mt][1], ah[mt][2], ah[mt][3],
                             bh[nt][0], bh[nt][1]);
                    mma_bf16(c[mt][nt], ah[mt][0], ah[mt][1], ah[mt][2], ah[mt][3],
                             bl[nt][0], bl[nt][1]);
                    mma_bf16(c[mt][nt], al[mt][0], al[mt][1], al[mt][2], al[mt][3],
                             bh[nt][0], bh[nt][1]);
                }
        }
    }

    // ------------------- Epilogue -------------------
    int quad = lane >> 2, qi = lane & 3;
    const float LG10000 = 13.2877123795494f;

    #pragma unroll
    for (int nt = 0; nt < 4; nt++) {
        int col = n0 + warpN + (nt << 3) + (qi << 1);
        float b0 = bias[col], b1 = bias[col + 1];
        if (MODE == 1) {
            #pragma unroll
            for (int mt = 0; mt < 4; mt++) {
                int r0 = m0 + warpM + (mt << 4) + quad;
                *(float2*)&out[(size_t)r0 * HIDDEN + col] =
                    make_float2(c[mt][nt][0] + b0, c[mt][nt][1] + b1);
                *(float2*)&out[(size_t)(r0 + 8) * HIDDEN + col] =
                    make_float2(c[mt][nt][2] + b0, c[mt][nt][3] + b1);
            }
        } else {
            int which = col >> 10;
            int h = (col >> 6) & 15;
            int d = col & 63;
            size_t hb = (size_t)h * SEQ * HD;
            if (which == 2) {
                #pragma unroll
                for (int mt = 0; mt < 4; mt++) {
                    int r0 = m0 + warpM + (mt << 4) + quad;
                    #pragma unroll
                    for (int rr = 0; rr < 2; rr++) {
                        int m = r0 + (rr << 3);
                        int bb = m >> 11, t = m & 2047;
                        size_t base = ((size_t)bb * NH) * SEQ * HD + hb + (size_t)t * HD + d;
                        uint32_t h32, l32;
                        split_pair(c[mt][nt][2*rr] + b0, c[mt][nt][2*rr+1] + b1, h32, l32);
                        *(uint32_t*)&g_vh[base] = h32;
                        *(uint32_t*)&g_vl[base] = l32;
                    }
                }
            } else {
                __nv_bfloat16* dsth = which ? g_kh : g_qh;
                __nv_bfloat16* dstl = which ? g_kl : g_ql;
                float qscale = which ? 1.0f : 0.125f;
                int p = d >> 1;
                float invf = exp2f(-((float)p * (1.0f / 32.0f)) * LG10000);
                #pragma unroll
                for (int mt = 0; mt < 4; mt++) {
                    int r0 = m0 + warpM + (mt << 4) + quad;
                    #pragma unroll
                    for (int rr = 0; rr < 2; rr++) {
                        int m = r0 + (rr << 3);
                        int bb = m >> 11, t = m & 2047;
                        float s, cc;
                        sincosf((float)t * invf, &s, &cc);
                        float x1 = c[mt][nt][2*rr] + b0;
                        float x2 = c[mt][nt][2*rr+1] + b1;
                        float r1 = (x1 * cc - x2 * s) * qscale;
                        float r2 = (x1 * s + x2 * cc) * qscale;
                        size_t base = ((size_t)bb * NH) * SEQ * HD + hb + (size_t)t * HD + d;
                        uint32_t h32, l32;
                        split_pair(r1, r2, h32, l32);
                        *(uint32_t*)&dsth[base] = h32;
                        *(uint32_t*)&dstl[base] = l32;
                    }
                }
            }
        }
    }
}

// ===========================================================================
// Tensor-core flash attention. 128 q-rows per CTA (8 warps x 16 rows),
// 64-key tiles, bf16 hi/lo split on both GEMMs (S = QK^T, O += P V).
// Q pre-scaled by 1/8. Online softmax on C-fragments (quad shuffles).
// ===========================================================================
#define ASTR 72
#define ATTN_SMEM (4 * 64 * ASTR * 2)   // 36864 B: Q stage (2x128x72) reuses same region

__global__ void __launch_bounds__(256) attn_kernel()
{
    extern __shared__ __nv_bfloat16 smA[];
    const uint32_t sbase = smem_to_u32(smA);

    int tid = threadIdx.x;
    int lane = tid & 31;
    int w = tid >> 5;
    int quad = lane >> 2, qi = lane & 3;
    int qt = gridDim.x - 1 - blockIdx.x;    // heavy tiles first
    int bh = blockIdx.y;
    size_t bh_base = (size_t)bh * SEQ * HD;

    // ---- Stage Q (hi at region 0, lo at region 1: each 128x72) ----
    #pragma unroll
    for (int i = 0; i < 8; i++) {
        int cidx = tid + (i << 8);                  // 0..2047
        int arr = cidx >> 10;
        int r = (cidx >> 3) & 127;
        int co = (cidx & 7) << 3;
        const __nv_bfloat16* src = arr ? g_ql : g_qh;
        uint4 v = *(const uint4*)&src[bh_base + (size_t)(qt * 128 + r) * HD + co];
        *(uint4*)&smA[arr * 128 * ASTR + r * ASTR + co] = v;
    }
    __syncthreads();

    // ---- Q fragments (A layout), kept in registers for the whole loop ----
    uint32_t qh[4][4], ql[4][4];
    {
        int arow = (w << 4) + (lane & 15);
        int akof = (lane >> 4) << 3;
        #pragma unroll
        for (int kk = 0; kk < 4; kk++) {
            uint32_t off = (arow * ASTR + (kk << 4) + akof) * 2;
            ldsm_x4(qh[kk][0], qh[kk][1], qh[kk][2], qh[kk][3], sbase + off);
            ldsm_x4(ql[kk][0], ql[kk][1], ql[kk][2], ql[kk][3],
                    sbase + 128 * ASTR * 2 + off);
        }
    }

    float o[8][4];
    #pragma unroll
    for (int nt = 0; nt < 8; nt++)
        #pragma unroll
        for (int r = 0; r < 4; r++) o[nt][r] = 0.f;
    float m0 = -1e30f, m1 = -1e30f, l0 = 0.f, l1 = 0.f;
    int rowA = qt * 128 + (w << 4) + quad;
    int rowB = rowA + 8;
    int wmaxrow = qt * 128 + (w << 4) + 15;

    int b_g = lane >> 3, b_i = lane & 7;
    int b_nof = (b_g >> 1) << 3;
    int b_kof = (b_g & 1) << 3;
    int v_row = lane & 15;
    int v_cof = (lane >> 4) << 3;
    const uint32_t KH = sbase;
    const uint32_t KL = sbase + 64 * ASTR * 2;
    const uint32_t VH = sbase + 2 * 64 * ASTR * 2;
    const uint32_t VL = sbase + 3 * 64 * ASTR * 2;

    int ktmax = 2 * qt + 1;
    for (int kt = 0; kt <= ktmax; kt++) {
        __syncthreads();   // previous K/V fully consumed
        // ---- Stage K/V hi+lo (4 regions of 64x72) ----
        #pragma unroll
        for (int i = 0; i < 8; i++) {
            int cidx = tid + (i << 8);              // 0..2047
            int arr = cidx >> 9;                    // 0=Kh 1=Kl 2=Vh 3=Vl
            int r = (cidx >> 3) & 63;
            int co = (cidx & 7) << 3;
            const __nv_bfloat16* src = (arr == 0) ? g_kh : (arr == 1) ? g_kl
                                     : (arr == 2) ? g_vh : g_vl;
            uint4 v = *(const uint4*)&src[bh_base + (size_t)(kt * 64 + r) * HD + co];
            *(uint4*)&smA[arr * 64 * ASTR + r * ASTR + co] = v;
        }
        __syncthreads();

        if (kt * 64 > wmaxrow) continue;   // whole warp masked (after syncs)

        // ---- S = Q K^T ----
        float s[8][4];
        #pragma unroll
        for (int nt = 0; nt < 8; nt++)
            #pragma unroll
            for (int r = 0; r < 4; r++) s[nt][r] = 0.f;
        #pragma unroll
        for (int kk = 0; kk < 4; kk++) {
            #pragma unroll
            for (int np = 0; np < 4; np++) {
                uint32_t off = (((np << 4) + b_nof + b_i) * ASTR + (kk << 4) + b_kof) * 2;
                uint32_t kb0, kb1, kb2, kb3, kc0, kc1, kc2, kc3;
                ldsm_x4(kb0, kb1, kb2, kb3, KH + off);
                ldsm_x4(kc0, kc1, kc2, kc3, KL + off);
                mma_bf16(s[2*np],   qh[kk][0], qh[kk][1], qh[kk][2], qh[kk][3], kb0, kb1);
                mma_bf16(s[2*np],   qh[kk][0], qh[kk][1], qh[kk][2], qh[kk][3], kc0, kc1);
                mma_bf16(s[2*np],   ql[kk][0], ql[kk][1], ql[kk][2], ql[kk][3], kb0, kb1);
                mma_bf16(s[2*np+1], qh[kk][0], qh[kk][1], qh[kk][2], qh[kk][3], kb2, kb3);
                mma_bf16(s[2*np+1], qh[kk][0], qh[kk][1], qh[kk][2], qh[kk][3], kc2, kc3);
                mma_bf16(s[2*np+1], ql[kk][0], ql[kk][1], ql[kk][2], ql[kk][3], kb2, kb3);
            }
        }

        // ---- causal mask (boundary tiles only) ----
        if (kt >= 2 * qt) {
            #pragma unroll
            for (int nt = 0; nt < 8; nt++) {
                int c0 = kt * 64 + (nt << 3) + (qi << 1);
                if (c0     > rowA) s[nt][0] = -1e9f;
                if (c0 + 1 > rowA) s[nt][1] = -1e9f;
                if (c0     > rowB) s[nt][2] = -1e9f;
                if (c0 + 1 > rowB) s[nt][3] = -1e9f;
            }
        }

        // ---- online softmax ----
        float mx0 = -1e30f, mx1 = -1e30f;
        #pragma unroll
        for (int nt = 0; nt < 8; nt++) {
            mx0 = fmaxf(mx0, fmaxf(s[nt][0], s[nt][1]));
            mx1 = fmaxf(mx1, fmaxf(s[nt][2], s[nt][3]));
        }
        mx0 = fmaxf(mx0, __shfl_xor_sync(0xffffffffu, mx0, 1));
        mx0 = fmaxf(mx0, __shfl_xor_sync(0xffffffffu, mx0, 2));
        mx1 = fmaxf(mx1, __shfl_xor_sync(0xffffffffu, mx1, 1));
        mx1 = fmaxf(mx1, __shfl_xor_sync(0xffffffffu, mx1, 2));
        float mn0 = fmaxf(m0, mx0), mn1 = fmaxf(m1, mx1);
        float a0 = __expf(m0 - mn0), a1 = __expf(m1 - mn1);
        float rs0 = 0.f, rs1 = 0.f;
        #pragma unroll
        for (int nt = 0; nt < 8; nt++) {
            s[nt][0] = __expf(s[nt][0] - mn0);
            s[nt][1] = __expf(s[nt][1] - mn0);
            s[nt][2] = __expf(s[nt][2] - mn1);
            s[nt][3] = __expf(s[nt][3] - mn1);
            rs0 += s[nt][0] + s[nt][1];
            rs1 += s[nt][2] + s[nt][3];
        }
        rs0 += __shfl_xor_sync(0xffffffffu, rs0, 1);
        rs0 += __shfl_xor_sync(0xffffffffu, rs0, 2);
        rs1 += __shfl_xor_sync(0xffffffffu, rs1, 1);
        rs1 += __shfl_xor_sync(0xffffffffu, rs1, 2);
        l0 = l0 * a0 + rs0;  l1 = l1 * a1 + rs1;
        m0 = mn0;  m1 = mn1;
        #pragma unroll
        for (int nt = 0; nt < 8; nt++) {
            o[nt][0] *= a0; o[nt][1] *= a0;
            o[nt][2] *= a1; o[nt][3] *= a1;
        }

        // ---- O += P V ----
        #pragma unroll
        for (int j = 0; j < 4; j++) {
            uint32_t pah[4], pal[4];
            split_pair(s[2*j][0],   s[2*j][1],   pah[0], pal[0]);
            split_pair(s[2*j][2],   s[2*j][3],   pah[1], pal[1]);
            split_pair(s[2*j+1][0], s[2*j+1][1], pah[2], pal[2]);
            split_pair(s[2*j+1][2], s[2*j+1][3], pah[3], pal[3]);
            #pragma unroll
            for (int np = 0; np < 4; np++) {
                uint32_t off = (((j << 4) + v_row) * ASTR + (np << 4) + v_cof) * 2;
                uint32_t vb0, vb1, vb2, vb3, vc0, vc1, vc2, vc3;
                ldsm_x4_t(vb0, vb1, vb2, vb3, VH + off);
                ldsm_x4_t(vc0, vc1, vc2, vc3, VL + off);
                mma_bf16(o[2*np],   pah[0], pah[1], pah[2], pah[3], vb0, vb1);
                mma_bf16(o[2*np],   pah[0], pah[1], pah[2], pah[3], vc0, vc1);
                mma_bf16(o[2*np],   pal[0], pal[1], pal[2], pal[3], vb0, vb1);
                mma_bf16(o[2*np+1], pah[0], pah[1], pah[2], pah[3], vb2, vb3);
                mma_bf16(o[2*np+1], pah[0], pah[1], pah[2], pah[3], vc2, vc3);
                mma_bf16(o[2*np+1], pal[0], pal[1], pal[2], pal[3], vb2, vb3);
            }
        }
    }

    // ---- epilogue: normalize, write [B,T,H*D] fp32 ----
    float i0 = 1.0f / l0, i1 = 1.0f / l1;
    int b = bh >> 4, h = bh & 15;
    size_t obaseA = ((size_t)b * SEQ + rowA) * HIDDEN + h * HD;
    size_t obaseB = ((size_t)b * SEQ + rowB) * HIDDEN + h * HD;
    #pragma unroll
    for (int nt = 0; nt < 8; nt++) {
        int col = (nt << 3) + (qi << 1);
        *(float2*)&g_att[obaseA + col] = make_float2(o[nt][0] * i0, o[nt][1] * i0);
        *(float2*)&g_att[obaseB + col] = make_float2(o[nt][2] * i1, o[nt][3] * i1);
    }
}

// ---------------------------------------------------------------------------
extern "C" void kernel_launch(void* const* d_in, const int* in_sizes, int n_in,
                              void* d_out, int out_size)
{
    const float* x    = (const float*)d_in[0];
    // d_in[1] = mask (bool) — pure causal, unused
    const float* Wqkv = (const float*)d_in[2];
    const float* bqkv = (const float*)d_in[3];
    const float* Wout = (const float*)d_in[4];
    const float* bout = (const float*)d_in[5];
    float* out = (float*)d_out;

    cudaFuncSetAttribute(gemm_tc_kernel<0>, cudaFuncAttributeMaxDynamicSharedMemorySize, GEMM_SMEM);
    cudaFuncSetAttribute(gemm_tc_kernel<1>, cudaFuncAttributeMaxDynamicSharedMemorySize, GEMM_SMEM);

    // QKV + bias + RoPE -> bf16-split q/k/v
    gemm_tc_kernel<0><<<dim3(BT/128, 3*HIDDEN/128), 256, GEMM_SMEM>>>(x, Wqkv, bqkv, nullptr);

    // Tensor-core flash attention
    attn_kernel<<<dim3(SEQ/128, BATCH*NH), 256, ATTN_SMEM>>>();

    // Out projection (reads g_att)
    gemm_tc_kernel<1><<<dim3(BT/128, HIDDEN/128), 256, GEMM_SMEM>>>(nullptr, Wout, bout, out);
}

// round 5
// speedup vs baseline: 3.3253x; 1.0756x over previous
#include <cuda_runtime.h>
#include <cuda_bf16.h>
#include <math.h>
#include <stdint.h>

#define HIDDEN 1024
#define NH 16
#define HD 64
#define BATCH 2
#define SEQ 2048
#define BT (BATCH*SEQ)   // 4096

// ---------------- bf16 hi/lo split scratch (device globals) ----------------
__device__ __nv_bfloat16 g_xh[BT*HIDDEN],  g_xl[BT*HIDDEN];
__device__ __nv_bfloat16 g_wqh[3*HIDDEN*HIDDEN], g_wql[3*HIDDEN*HIDDEN];
__device__ __nv_bfloat16 g_woh[HIDDEN*HIDDEN],   g_wol[HIDDEN*HIDDEN];
__device__ __nv_bfloat16 g_qh[BT*HIDDEN], g_ql[BT*HIDDEN];   // [b,h,t,d], q pre-scaled 1/8
__device__ __nv_bfloat16 g_kh[BT*HIDDEN], g_kl[BT*HIDDEN];
__device__ __nv_bfloat16 g_vh[BT*HIDDEN], g_vl[BT*HIDDEN];
__device__ __nv_bfloat16 g_atth[BT*HIDDEN], g_attl[BT*HIDDEN];  // [b,t,h*64+d]

// ===========================================================================
// Primitives
// ===========================================================================
__device__ __forceinline__ uint32_t smem_to_u32(const void* smem_ptr) {
    uint32_t addr;
    asm("{ .reg .u64 tmp; cvta.to.shared.u64 tmp, %1; cvt.u32.u64 %0, tmp; }"
        : "=r"(addr) : "l"(smem_ptr));
    return addr;
}
__device__ __forceinline__ void ldsm_x4(uint32_t& r0, uint32_t& r1,
                                        uint32_t& r2, uint32_t& r3, uint32_t addr) {
    asm volatile("ldmatrix.sync.aligned.m8n8.x4.shared.b16 {%0,%1,%2,%3}, [%4];"
                 : "=r"(r0), "=r"(r1), "=r"(r2), "=r"(r3) : "r"(addr));
}
__device__ __forceinline__ void ldsm_x4_t(uint32_t& r0, uint32_t& r1,
                                          uint32_t& r2, uint32_t& r3, uint32_t addr) {
    asm volatile("ldmatrix.sync.aligned.m8n8.x4.trans.shared.b16 {%0,%1,%2,%3}, [%4];"
                 : "=r"(r0), "=r"(r1), "=r"(r2), "=r"(r3) : "r"(addr));
}
__device__ __forceinline__ void mma_bf16(float* c,
                                         uint32_t a0, uint32_t a1, uint32_t a2, uint32_t a3,
                                         uint32_t b0, uint32_t b1) {
    asm volatile(
        "mma.sync.aligned.m16n8k16.row.col.f32.bf16.bf16.f32 "
        "{%0,%1,%2,%3}, {%4,%5,%6,%7}, {%8,%9}, {%0,%1,%2,%3};"
        : "+f"(c[0]), "+f"(c[1]), "+f"(c[2]), "+f"(c[3])
        : "r"(a0), "r"(a1), "r"(a2), "r"(a3), "r"(b0), "r"(b1));
}
__device__ __forceinline__ void split_pair(float x1, float x2, uint32_t& h, uint32_t& l) {
    __nv_bfloat162 hh = __floats2bfloat162_rn(x1, x2);
    float2 hf = __bfloat1622float2(hh);
    __nv_bfloat162 ll = __floats2bfloat162_rn(x1 - hf.x, x2 - hf.y);
    h = *reinterpret_cast<uint32_t*>(&hh);
    l = *reinterpret_cast<uint32_t*>(&ll);
}

#define CP_ASYNC16(sm, gp) \
    asm volatile("cp.async.cg.shared.global [%0], [%1], 16;" :: "r"(sm), "l"(gp))
#define CP_COMMIT() asm volatile("cp.async.commit_group;" ::: "memory")
#define CP_WAIT1() asm volatile("cp.async.wait_group 1;" ::: "memory")
#define CP_WAIT0() asm volatile("cp.async.wait_group 0;" ::: "memory")

// ===========================================================================
// Prep: fp32 -> bf16 hi/lo split (grid-stride over float4)
// ===========================================================================
__global__ void __launch_bounds__(256) split_kernel(
    const float4* __restrict__ src, uint2* __restrict__ h, uint2* __restrict__ l, int n4)
{
    int i = blockIdx.x * blockDim.x + threadIdx.x;
    if (i < n4) {
        float4 v = src[i];
        uint32_t h01, l01, h23, l23;
        split_pair(v.x, v.y, h01, l01);
        split_pair(v.z, v.w, h23, l23);
        h[i] = make_uint2(h01, h23);
        l[i] = make_uint2(l01, l23);
    }
}

// ===========================================================================
// HMMA GEMM, cp.async double-buffered. CTA 128x128, K-chunks of 32 (32 chunks).
// Tiles 128x32 bf16, XOR swizzle: seg^( (r>>1)&3 ) — conflict-free LDSM.
// MODE 0: A=x split, B=Wqkv split, epilogue bias+RoPE -> q/k/v splits.
// MODE 1: A=att split, B=Wout split, epilogue bias -> fp32 out.
// ===========================================================================
#define GTILE_B 8192
#define GBUF_B  32768            // 4 tiles (Ah,Al,Bh,Bl)
#define GEMM_SMEM 65536          // 2 buffers

__device__ __forceinline__ uint32_t gswz(int r, int c) {
    int seg = (c >> 3) ^ ((r >> 1) & 3);
    return (uint32_t)((r << 5) + (seg << 3) + (c & 7));
}

template<int MODE>
__global__ void __launch_bounds__(256) gemm_tc_kernel(
    const float* __restrict__ bias, float* __restrict__ out)
{
    extern __shared__ char smem[];
    const uint32_t sbase = smem_to_u32(smem);

    const __nv_bfloat16* Ah = (MODE == 0) ? g_xh : g_atth;
    const __nv_bfloat16* Al = (MODE == 0) ? g_xl : g_attl;
    const __nv_bfloat16* Bh = (MODE == 0) ? g_wqh : g_woh;
    const __nv_bfloat16* Bl = (MODE == 0) ? g_wql : g_wol;

    int tid = threadIdx.x, lane = tid & 31, wid = tid >> 5;
    int warpM = (wid & 1) << 6, warpN = (wid >> 1) << 5;
    int m0 = blockIdx.x * 128, n0 = blockIdx.y * 128;

    // staging: each thread covers 4 tiles x rows {r0, r0+64} x one 16B seg
    int r0 = tid >> 2, s8 = (tid & 3) << 3;
    uint32_t sm0 = gswz(r0, s8) * 2;
    uint32_t sm1 = gswz(r0 + 64, s8) * 2;
    const __nv_bfloat16* gAh = Ah + (size_t)(m0 + r0) * HIDDEN + s8;
    const __nv_bfloat16* gAl = Al + (size_t)(m0 + r0) * HIDDEN + s8;
    const __nv_bfloat16* gBh = Bh + (size_t)(n0 + r0) * HIDDEN + s8;
    const __nv_bfloat16* gBl = Bl + (size_t)(n0 + r0) * HIDDEN + s8;
    const size_t R64 = (size_t)64 * HIDDEN;

    int a_row = lane & 15, a_kof = (lane >> 4) << 3;
    int b_g = lane >> 3, b_i = lane & 7;
    int b_nof = (b_g >> 1) << 3, b_kof = (b_g & 1) << 3;

    float c[4][4][4];
    #pragma unroll
    for (int mt = 0; mt < 4; mt++)
        #pragma unroll
        for (int nt = 0; nt < 4; nt++)
            #pragma unroll
            for (int r = 0; r < 4; r++) c[mt][nt][r] = 0.f;

    auto issue = [&](int ch, int buf) {
        uint32_t b = sbase + buf * GBUF_B;
        int k0 = ch << 5;
        CP_ASYNC16(b + sm0,               gAh + k0);
        CP_ASYNC16(b + sm1,               gAh + R64 + k0);
        CP_ASYNC16(b + GTILE_B + sm0,     gAl + k0);
        CP_ASYNC16(b + GTILE_B + sm1,     gAl + R64 + k0);
        CP_ASYNC16(b + 2*GTILE_B + sm0,   gBh + k0);
        CP_ASYNC16(b + 2*GTILE_B + sm1,   gBh + R64 + k0);
        CP_ASYNC16(b + 3*GTILE_B + sm0,   gBl + k0);
        CP_ASYNC16(b + 3*GTILE_B + sm1,   gBl + R64 + k0);
        CP_COMMIT();
    };

    issue(0, 0);
    #pragma unroll 1
    for (int ch = 0; ch < 32; ch++) {
        if (ch + 1 < 32) { issue(ch + 1, (ch + 1) & 1); CP_WAIT1(); }
        else             { CP_WAIT0(); }
        __syncthreads();
        uint32_t base = sbase + (ch & 1) * GBUF_B;
        #pragma unroll
        for (int k16 = 0; k16 < 2; k16++) {
            int kk = k16 << 4;
            uint32_t ah[4][4], al[4][4], bh[4][2], bl[4][2];
            #pragma unroll
            for (int mt = 0; mt < 4; mt++) {
                uint32_t off = gswz(warpM + (mt << 4) + a_row, kk + a_kof) * 2;
                ldsm_x4(ah[mt][0], ah[mt][1], ah[mt][2], ah[mt][3], base + off);
                ldsm_x4(al[mt][0], al[mt][1], al[mt][2], al[mt][3], base + GTILE_B + off);
            }
            #pragma unroll
            for (int np = 0; np < 2; np++) {
                uint32_t off = gswz(warpN + (np << 4) + b_nof + b_i, kk + b_kof) * 2;
                ldsm_x4(bh[2*np][0], bh[2*np][1], bh[2*np+1][0], bh[2*np+1][1],
                        base + 2*GTILE_B + off);
                ldsm_x4(bl[2*np][0], bl[2*np][1], bl[2*np+1][0], bl[2*np+1][1],
                        base + 3*GTILE_B + off);
            }
            #pragma unroll
            for (int mt = 0; mt < 4; mt++)
                #pragma unroll
                for (int nt = 0; nt < 4; nt++) {
                    mma_bf16(c[mt][nt], ah[mt][0], ah[mt][1], ah[mt][2], ah[mt][3],
                             bh[nt][0], bh[nt][1]);
                    mma_bf16(c[mt][nt], ah[mt][0], ah[mt][1], ah[mt][2], ah[mt][3],
                             bl[nt][0], bl[nt][1]);
                    mma_bf16(c[mt][nt], al[mt][0], al[mt][1], al[mt][2], al[mt][3],
                             bh[nt][0], bh[nt][1]);
                }
        }
        __syncthreads();
    }

    // ------------------- Epilogue -------------------
    int quad = lane >> 2, qi = lane & 3;
    const float LG10000 = 13.2877123795494f;

    #pragma unroll
    for (int nt = 0; nt < 4; nt++) {
        int col = n0 + warpN + (nt << 3) + (qi << 1);
        float b0 = bias[col], b1 = bias[col + 1];
        if (MODE == 1) {
            #pragma unroll
            for (int mt = 0; mt < 4; mt++) {
                int r0m = m0 + warpM + (mt << 4) + quad;
                *(float2*)&out[(size_t)r0m * HIDDEN + col] =
                    make_float2(c[mt][nt][0] + b0, c[mt][nt][1] + b1);
                *(float2*)&out[(size_t)(r0m + 8) * HIDDEN + col] =
                    make_float2(c[mt][nt][2] + b0, c[mt][nt][3] + b1);
            }
        } else {
            int which = col >> 10;
            int h = (col >> 6) & 15;
            int d = col & 63;
            size_t hb = (size_t)h * SEQ * HD;
            if (which == 2) {
                #pragma unroll
                for (int mt = 0; mt < 4; mt++) {
                    int r0m = m0 + warpM + (mt << 4) + quad;
                    #pragma unroll
                    for (int rr = 0; rr < 2; rr++) {
                        int m = r0m + (rr << 3);
                        int bb = m >> 11, t = m & 2047;
                        size_t base = ((size_t)bb * NH) * SEQ * HD + hb + (size_t)t * HD + d;
                        uint32_t h32, l32;
                        split_pair(c[mt][nt][2*rr] + b0, c[mt][nt][2*rr+1] + b1, h32, l32);
                        *(uint32_t*)&g_vh[base] = h32;
                        *(uint32_t*)&g_vl[base] = l32;
                    }
                }
            } else {
                __nv_bfloat16* dsth = which ? g_kh : g_qh;
                __nv_bfloat16* dstl = which ? g_kl : g_ql;
                float qscale = which ? 1.0f : 0.125f;
                int p = d >> 1;
                float invf = exp2f(-((float)p * (1.0f / 32.0f)) * LG10000);
                #pragma unroll
                for (int mt = 0; mt < 4; mt++) {
                    int r0m = m0 + warpM + (mt << 4) + quad;
                    #pragma unroll
                    for (int rr = 0; rr < 2; rr++) {
                        int m = r0m + (rr << 3);
                        int bb = m >> 11, t = m & 2047;
                        float s, cc;
                        sincosf((float)t * invf, &s, &cc);
                        float x1 = c[mt][nt][2*rr] + b0;
                        float x2 = c[mt][nt][2*rr+1] + b1;
                        float r1 = (x1 * cc - x2 * s) * qscale;
                        float r2 = (x1 * s + x2 * cc) * qscale;
                        size_t base = ((size_t)bb * NH) * SEQ * HD + hb + (size_t)t * HD + d;
                        uint32_t h32, l32;
                        split_pair(r1, r2, h32, l32);
                        *(uint32_t*)&dsth[base] = h32;
                        *(uint32_t*)&dstl[base] = l32;
                    }
                }
            }
        }
    }
}

// ===========================================================================
// Tensor-core flash attention, cp.async double-buffered K/V.
// 128 q-rows/CTA (8 warps x 16 rows), 64-key tiles, XOR swizzle seg^(r&7).
// ===========================================================================
#define ATILE_B 8192
#define ABUF_B  32768            // Kh,Kl,Vh,Vl
#define ATTN_SMEM 65536

__device__ __forceinline__ uint32_t aswz(int r, int c) {
    int seg = (c >> 3) ^ (r & 7);
    return (uint32_t)((r << 6) + (seg << 3) + (c & 7));
}

__global__ void __launch_bounds__(256) attn_kernel()
{
    extern __shared__ char smemc[];
    const uint32_t sbase = smem_to_u32(smemc);

    int tid = threadIdx.x;
    int lane = tid & 31;
    int w = tid >> 5;
    int quad = lane >> 2, qi = lane & 3;
    int qt = gridDim.x - 1 - blockIdx.x;    // heavy tiles first
    int bh = blockIdx.y;
    size_t bh_base = (size_t)bh * SEQ * HD;

    // ---- Stage Q (qh at +0, ql at +16384; 128x64 swizzled each) ----
    #pragma unroll
    for (int i = 0; i < 8; i++) {
        int cidx = tid + (i << 8);               // 0..2047
        int arr = cidx >> 10;
        int r = (cidx >> 3) & 127;
        int sg = (cidx & 7) << 3;
        const __nv_bfloat16* src = arr ? g_ql : g_qh;
        uint4 v = *(const uint4*)&src[bh_base + (size_t)(qt * 128 + r) * HD + sg];
        *(uint4*)(smemc + arr * 16384 + aswz(r, sg) * 2) = v;
    }
    __syncthreads();

    // ---- Q fragments ----
    uint32_t qh[4][4], ql[4][4];
    {
        int arow = (w << 4) + (lane & 15);
        int akof = (lane >> 4) << 3;
        #pragma unroll
        for (int kk = 0; kk < 4; kk++) {
            uint32_t off = aswz(arow, (kk << 4) + akof) * 2;
            ldsm_x4(qh[kk][0], qh[kk][1], qh[kk][2], qh[kk][3], sbase + off);
            ldsm_x4(ql[kk][0], ql[kk][1], ql[kk][2], ql[kk][3], sbase + 16384 + off);
        }
    }
    __syncthreads();   // frags extracted; buffer free for K/V

    // ---- K/V staging setup: each thread: 4 tiles x rows {r0, r0+32} x one seg
    int r0 = tid >> 3, s8 = (tid & 7) << 3;
    uint32_t asm0 = aswz(r0, s8) * 2;
    uint32_t asm1 = aswz(r0 + 32, s8) * 2;
    const __nv_bfloat16* gKh = g_kh + bh_base + (size_t)r0 * HD + s8;
    const __nv_bfloat16* gKl = g_kl + bh_base + (size_t)r0 * HD + s8;
    const __nv_bfloat16* gVh = g_vh + bh_base + (size_t)r0 * HD + s8;
    const __nv_bfloat16* gVl = g_vl + bh_base + (size_t)r0 * HD + s8;
    const size_t R32 = (size_t)32 * HD;

    auto issue = [&](int kt, int buf) {
        uint32_t b = sbase + buf * ABUF_B;
        size_t k0 = (size_t)kt << 12;            // kt*64*64 elems
        CP_ASYNC16(b + asm0,               gKh + k0);
        CP_ASYNC16(b + asm1,               gKh + k0 + R32);
        CP_ASYNC16(b + ATILE_B + asm0,     gKl + k0);
        CP_ASYNC16(b + ATILE_B + asm1,     gKl + k0 + R32);
        CP_ASYNC16(b + 2*ATILE_B + asm0,   gVh + k0);
        CP_ASYNC16(b + 2*ATILE_B + asm1,   gVh + k0 + R32);
        CP_ASYNC16(b + 3*ATILE_B + asm0,   gVl + k0);
        CP_ASYNC16(b + 3*ATILE_B + asm1,   gVl + k0 + R32);
        CP_COMMIT();
    };

    float o[8][4];
    #pragma unroll
    for (int nt = 0; nt < 8; nt++)
        #pragma unroll
        for (int r = 0; r < 4; r++) o[nt][r] = 0.f;
    float m0 = -1e30f, m1 = -1e30f, l0 = 0.f, l1 = 0.f;
    int rowA = qt * 128 + (w << 4) + quad;
    int rowB = rowA + 8;
    int wmaxrow = qt * 128 + (w << 4) + 15;

    int b_g = lane >> 3, b_i = lane & 7;
    int b_nof = (b_g >> 1) << 3;
    int b_kof = (b_g & 1) << 3;
    int v_row = lane & 15;
    int v_cof = (lane >> 4) << 3;

    int ktmax = 2 * qt + 1;
    issue(0, 0);
    #pragma unroll 1
    for (int kt = 0; kt <= ktmax; kt++) {
        if (kt + 1 <= ktmax) { issue(kt + 1, (kt + 1) & 1); CP_WAIT1(); }
        else                 { CP_WAIT0(); }
        __syncthreads();

        if (kt * 64 <= wmaxrow) {
            uint32_t base = sbase + (kt & 1) * ABUF_B;
            const uint32_t KH = base, KL = base + ATILE_B;
            const uint32_t VH = base + 2*ATILE_B, VL = base + 3*ATILE_B;

            // ---- S = Q K^T ----
            float s[8][4];
            #pragma unroll
            for (int nt = 0; nt < 8; nt++)
                #pragma unroll
                for (int r = 0; r < 4; r++) s[nt][r] = 0.f;
            #pragma unroll
            for (int kk = 0; kk < 4; kk++) {
                #pragma unroll
                for (int np = 0; np < 4; np++) {
                    uint32_t off = aswz((np << 4) + b_nof + b_i, (kk << 4) + b_kof) * 2;
                    uint32_t kb0, kb1, kb2, kb3, kc0, kc1, kc2, kc3;
                    ldsm_x4(kb0, kb1, kb2, kb3, KH + off);
                    ldsm_x4(kc0, kc1, kc2, kc3, KL + off);
                    mma_bf16(s[2*np],   qh[kk][0], qh[kk][1], qh[kk][2], qh[kk][3], kb0, kb1);
                    mma_bf16(s[2*np],   qh[kk][0], qh[kk][1], qh[kk][2], qh[kk][3], kc0, kc1);
                    mma_bf16(s[2*np],   ql[kk][0], ql[kk][1], ql[kk][2], ql[kk][3], kb0, kb1);
                    mma_bf16(s[2*np+1], qh[kk][0], qh[kk][1], qh[kk][2], qh[kk][3], kb2, kb3);
                    mma_bf16(s[2*np+1], qh[kk][0], qh[kk][1], qh[kk][2], qh[kk][3], kc2, kc3);
                    mma_bf16(s[2*np+1], ql[kk][0], ql[kk][1], ql[kk][2], ql[kk][3], kb2, kb3);
                }
            }

            // ---- causal mask (boundary tiles only) ----
            if (kt >= 2 * qt) {
                #pragma unroll
                for (int nt = 0; nt < 8; nt++) {
                    int c0 = kt * 64 + (nt << 3) + (qi << 1);
                    if (c0     > rowA) s[nt][0] = -1e9f;
                    if (c0 + 1 > rowA) s[nt][1] = -1e9f;
                    if (c0     > rowB) s[nt][2] = -1e9f;
                    if (c0 + 1 > rowB) s[nt][3] = -1e9f;
                }
            }

            // ---- online softmax ----
            float mx0 = -1e30f, mx1 = -1e30f;
            #pragma unroll
            for (int nt = 0; nt < 8; nt++) {
                mx0 = fmaxf(mx0, fmaxf(s[nt][0], s[nt][1]));
                mx1 = fmaxf(mx1, fmaxf(s[nt][2], s[nt][3]));
            }
            mx0 = fmaxf(mx0, __shfl_xor_sync(0xffffffffu, mx0, 1));
            mx0 = fmaxf(mx0, __shfl_xor_sync(0xffffffffu, mx0, 2));
            mx1 = fmaxf(mx1, __shfl_xor_sync(0xffffffffu, mx1, 1));
            mx1 = fmaxf(mx1, __shfl_xor_sync(0xffffffffu, mx1, 2));
            float mn0 = fmaxf(m0, mx0), mn1 = fmaxf(m1, mx1);
            float a0 = __expf(m0 - mn0), a1 = __expf(m1 - mn1);
            float rs0 = 0.f, rs1 = 0.f;
            #pragma unroll
            for (int nt = 0; nt < 8; nt++) {
                s[nt][0] = __expf(s[nt][0] - mn0);
                s[nt][1] = __expf(s[nt][1] - mn0);
                s[nt][2] = __expf(s[nt][2] - mn1);
                s[nt][3] = __expf(s[nt][3] - mn1);
                rs0 += s[nt][0] + s[nt][1];
                rs1 += s[nt][2] + s[nt][3];
            }
            rs0 += __shfl_xor_sync(0xffffffffu, rs0, 1);
            rs0 += __shfl_xor_sync(0xffffffffu, rs0, 2);
            rs1 += __shfl_xor_sync(0xffffffffu, rs1, 1);
            rs1 += __shfl_xor_sync(0xffffffffu, rs1, 2);
            l0 = l0 * a0 + rs0;  l1 = l1 * a1 + rs1;
            m0 = mn0;  m1 = mn1;
            #pragma unroll
            for (int nt = 0; nt < 8; nt++) {
                o[nt][0] *= a0; o[nt][1] *= a0;
                o[nt][2] *= a1; o[nt][3] *= a1;
            }

            // ---- O += P V ----
            #pragma unroll
            for (int j = 0; j < 4; j++) {
                uint32_t pah[4], pal[4];
                split_pair(s[2*j][0],   s[2*j][1],   pah[0], pal[0]);
                split_pair(s[2*j][2],   s[2*j][3],   pah[1], pal[1]);
                split_pair(s[2*j+1][0], s[2*j+1][1], pah[2], pal[2]);
                split_pair(s[2*j+1][2], s[2*j+1][3], pah[3], pal[3]);
                #pragma unroll
                for (int np = 0; np < 4; np++) {
                    uint32_t off = aswz((j << 4) + v_row, (np << 4) + v_cof) * 2;
                    uint32_t vb0, vb1, vb2, vb3, vc0, vc1, vc2, vc3;
                    ldsm_x4_t(vb0, vb1, vb2, vb3, VH + off);
                    ldsm_x4_t(vc0, vc1, vc2, vc3, VL + off);
                    mma_bf16(o[2*np],   pah[0], pah[1], pah[2], pah[3], vb0, vb1);
                    mma_bf16(o[2*np],   pah[0], pah[1], pah[2], pah[3], vc0, vc1);
                    mma_bf16(o[2*np],   pal[0], pal[1], pal[2], pal[3], vb0, vb1);
                    mma_bf16(o[2*np+1], pah[0], pah[1], pah[2], pah[3], vb2, vb3);
                    mma_bf16(o[2*np+1], pah[0], pah[1], pah[2], pah[3], vc2, vc3);
                    mma_bf16(o[2*np+1], pal[0], pal[1], pal[2], pal[3], vb2, vb3);
                }
            }
        }
        __syncthreads();
    }

    // ---- epilogue: normalize, split to bf16 hi/lo [B,T,H*D] ----
    float i0 = 1.0f / l0, i1 = 1.0f / l1;
    int b = bh >> 4, h = bh & 15;
    size_t obaseA = ((size_t)b * SEQ + rowA) * HIDDEN + h * HD;
    size_t obaseB = ((size_t)b * SEQ + rowB) * HIDDEN + h * HD;
    #pragma unroll
    for (int nt = 0; nt < 8; nt++) {
        int col = (nt << 3) + (qi << 1);
        uint32_t h32, l32;
        split_pair(o[nt][0] * i0, o[nt][1] * i0, h32, l32);
        *(uint32_t*)&g_atth[obaseA + col] = h32;
        *(uint32_t*)&g_attl[obaseA + col] = l32;
        split_pair(o[nt][2] * i1, o[nt][3] * i1, h32, l32);
        *(uint32_t*)&g_atth[obaseB + col] = h32;
        *(uint32_t*)&g_attl[obaseB + col] = l32;
    }
}

// ---------------------------------------------------------------------------
extern "C" void kernel_launch(void* const* d_in, const int* in_sizes, int n_in,
                              void* d_out, int out_size)
{
    const float* x    = (const float*)d_in[0];
    // d_in[1] = mask (bool) — pure causal, unused
    const float* Wqkv = (const float*)d_in[2];
    const float* bqkv = (const float*)d_in[3];
    const float* Wout = (const float*)d_in[4];
    const float* bout = (const float*)d_in[5];
    float* out = (float*)d_out;

    void *xh, *xl, *wqh, *wql, *woh, *wol;
    cudaGetSymbolAddress(&xh,  g_xh);  cudaGetSymbolAddress(&xl,  g_xl);
    cudaGetSymbolAddress(&wqh, g_wqh); cudaGetSymbolAddress(&wql, g_wql);
    cudaGetSymbolAddress(&woh, g_woh); cudaGetSymbolAddress(&wol, g_wol);

    cudaFuncSetAttribute(gemm_tc_kernel<0>, cudaFuncAttributeMaxDynamicSharedMemorySize, GEMM_SMEM);
    cudaFuncSetAttribute(gemm_tc_kernel<1>, cudaFuncAttributeMaxDynamicSharedMemorySize, GEMM_SMEM);
    cudaFuncSetAttribute(attn_kernel, cudaFuncAttributeMaxDynamicSharedMemorySize, ATTN_SMEM);

    // Pre-split inputs to bf16 hi/lo
    split_kernel<<<(BT*HIDDEN/4 + 255)/256, 256>>>((const float4*)x,
        (uint2*)xh, (uint2*)xl, BT*HIDDEN/4);
    split_kernel<<<(3*HIDDEN*HIDDEN/4 + 255)/256, 256>>>((const float4*)Wqkv,
        (uint2*)wqh, (uint2*)wql, 3*HIDDEN*HIDDEN/4);
    split_kernel<<<(HIDDEN*HIDDEN/4 + 255)/256, 256>>>((const float4*)Wout,
        (uint2*)woh, (uint2*)wol, HIDDEN*HIDDEN/4);

    // QKV + bias + RoPE -> q/k/v splits
    gemm_tc_kernel<0><<<dim3(BT/128, 3*HIDDEN/128), 256, GEMM_SMEM>>>(bqkv, nullptr);

    // Flash attention -> att splits
    attn_kernel<<<dim3(SEQ/128, BATCH*NH), 256, ATTN_SMEM>>>();

    // Out projection -> fp32 out
    gemm_tc_kernel<1><<<dim3(BT/128, HIDDEN/128), 256, GEMM_SMEM>>>(bout, out);
}

// round 6
// speedup vs baseline: 4.5441x; 1.3665x over previous
#include <cuda_runtime.h>
#include <cuda_fp16.h>
#include <math.h>
#include <stdint.h>

#define HIDDEN 1024
#define NH 16
#define HD 64
#define BATCH 2
#define SEQ 2048
#define BT (BATCH*SEQ)   // 4096

// ---------------- fp16 scratch (device globals) ----------------
// Singles are rounded fp32->fp16; h/l pairs are exact two-term splits.
__device__ __half g_xs[BT*HIDDEN];                              // x rounded
__device__ __half g_wqh[3*HIDDEN*HIDDEN], g_wql[3*HIDDEN*HIDDEN];
__device__ __half g_woh[HIDDEN*HIDDEN],   g_wol[HIDDEN*HIDDEN];
__device__ __half g_qs[BT*HIDDEN];                              // q rounded, pre-scaled 1/8
__device__ __half g_kh[BT*HIDDEN], g_kl[BT*HIDDEN];
__device__ __half g_vh[BT*HIDDEN], g_vl[BT*HIDDEN];
__device__ __half g_atts[BT*HIDDEN];                            // attn out rounded

// ===========================================================================
// Primitives
// ===========================================================================
__device__ __forceinline__ uint32_t smem_to_u32(const void* smem_ptr) {
    uint32_t addr;
    asm("{ .reg .u64 tmp; cvta.to.shared.u64 tmp, %1; cvt.u32.u64 %0, tmp; }"
        : "=r"(addr) : "l"(smem_ptr));
    return addr;
}
__device__ __forceinline__ void ldsm_x4(uint32_t& r0, uint32_t& r1,
                                        uint32_t& r2, uint32_t& r3, uint32_t addr) {
    asm volatile("ldmatrix.sync.aligned.m8n8.x4.shared.b16 {%0,%1,%2,%3}, [%4];"
                 : "=r"(r0), "=r"(r1), "=r"(r2), "=r"(r3) : "r"(addr));
}
__device__ __forceinline__ void ldsm_x4_t(uint32_t& r0, uint32_t& r1,
                                          uint32_t& r2, uint32_t& r3, uint32_t addr) {
    asm volatile("ldmatrix.sync.aligned.m8n8.x4.trans.shared.b16 {%0,%1,%2,%3}, [%4];"
                 : "=r"(r0), "=r"(r1), "=r"(r2), "=r"(r3) : "r"(addr));
}
__device__ __forceinline__ void mma_f16(float* c,
                                        uint32_t a0, uint32_t a1, uint32_t a2, uint32_t a3,
                                        uint32_t b0, uint32_t b1) {
    asm volatile(
        "mma.sync.aligned.m16n8k16.row.col.f32.f16.f16.f32 "
        "{%0,%1,%2,%3}, {%4,%5,%6,%7}, {%8,%9}, {%0,%1,%2,%3};"
        : "+f"(c[0]), "+f"(c[1]), "+f"(c[2]), "+f"(c[3])
        : "r"(a0), "r"(a1), "r"(a2), "r"(a3), "r"(b0), "r"(b1));
}
__device__ __forceinline__ uint32_t pack16(float x1, float x2) {
    __half2 h = __floats2half2_rn(x1, x2);
    return *reinterpret_cast<uint32_t*>(&h);
}
__device__ __forceinline__ void split16(float x1, float x2, uint32_t& h, uint32_t& l) {
    __half2 hh = __floats2half2_rn(x1, x2);
    float2 hf = __half22float2(hh);
    __half2 ll = __floats2half2_rn(x1 - hf.x, x2 - hf.y);
    h = *reinterpret_cast<uint32_t*>(&hh);
    l = *reinterpret_cast<uint32_t*>(&ll);
}

#define CP_ASYNC16(sm, gp) \
    asm volatile("cp.async.cg.shared.global [%0], [%1], 16;" :: "r"(sm), "l"(gp))
#define CP_COMMIT() asm volatile("cp.async.commit_group;" ::: "memory")
#define CP_WAIT1() asm volatile("cp.async.wait_group 1;" ::: "memory")

// ===========================================================================
// Prep kernels
// ===========================================================================
__global__ void __launch_bounds__(256) split_w_kernel(
    const float4* __restrict__ src, uint2* __restrict__ h, uint2* __restrict__ l, int n4)
{
    int i = blockIdx.x * blockDim.x + threadIdx.x;
    if (i < n4) {
        float4 v = src[i];
        uint32_t h01, l01, h23, l23;
        split16(v.x, v.y, h01, l01);
        split16(v.z, v.w, h23, l23);
        h[i] = make_uint2(h01, h23);
        l[i] = make_uint2(l01, l23);
    }
}
__global__ void __launch_bounds__(256) round_x_kernel(
    const float4* __restrict__ src, uint2* __restrict__ s, int n4)
{
    int i = blockIdx.x * blockDim.x + threadIdx.x;
    if (i < n4) {
        float4 v = src[i];
        s[i] = make_uint2(pack16(v.x, v.y), pack16(v.z, v.w));
    }
}

// ===========================================================================
// HMMA GEMM: C[4096, N] = A[4096,1024] @ (Bh+Bl)[N,1024]^T, A single fp16.
// CTA 128x128, 8 warps (2Mx4N, warp 64x32), K-chunks of 32, 3-stage cp.async.
// Per-buf: A 8KB + Bh 8KB + Bl 8KB = 24KB; XOR swizzle seg^((r>>1)&3).
// MODE 0: bias+RoPE -> q single / k,v splits. MODE 1: bias -> fp32 out.
// ===========================================================================
#define GTILE_B 8192
#define GBUF_B  24576
#define GEMM_SMEM (3 * GBUF_B)   // 73728

__device__ __forceinline__ uint32_t gswz(int r, int c) {
    int seg = (c >> 3) ^ ((r >> 1) & 3);
    return (uint32_t)((r << 5) + (seg << 3) + (c & 7));
}

template<int MODE>
__global__ void __launch_bounds__(256, 2) gemm_tc_kernel(
    const float* __restrict__ bias, float* __restrict__ out)
{
    extern __shared__ char smem[];
    const uint32_t sbase = smem_to_u32(smem);

    const __half* As = (MODE == 0) ? g_xs  : g_atts;
    const __half* Bh = (MODE == 0) ? g_wqh : g_woh;
    const __half* Bl = (MODE == 0) ? g_wql : g_wol;

    int tid = threadIdx.x, lane = tid & 31, wid = tid >> 5;
    int warpM = (wid & 1) << 6, warpN = (wid >> 1) << 5;
    int m0 = blockIdx.x * 128, n0 = blockIdx.y * 128;

    int r0 = tid >> 2, s8 = (tid & 3) << 3;
    uint32_t sm0 = gswz(r0, s8) * 2;
    uint32_t sm1 = gswz(r0 + 64, s8) * 2;
    const __half* gAs = As + (size_t)(m0 + r0) * HIDDEN + s8;
    const __half* gBh = Bh + (size_t)(n0 + r0) * HIDDEN + s8;
    const __half* gBl = Bl + (size_t)(n0 + r0) * HIDDEN + s8;
    const size_t R64 = (size_t)64 * HIDDEN;

    int a_row = lane & 15, a_kof = (lane >> 4) << 3;
    int b_g = lane >> 3, b_i = lane & 7;
    int b_nof = (b_g >> 1) << 3, b_kof = (b_g & 1) << 3;

    float c[4][4][4];
    #pragma unroll
    for (int mt = 0; mt < 4; mt++)
        #pragma unroll
        for (int nt = 0; nt < 4; nt++)
            #pragma unroll
            for (int r = 0; r < 4; r++) c[mt][nt][r] = 0.f;

    auto issue = [&](int ch) {
        uint32_t b = sbase + (ch % 3) * GBUF_B;
        int k0 = ch << 5;
        CP_ASYNC16(b + sm0,             gAs + k0);
        CP_ASYNC16(b + sm1,             gAs + R64 + k0);
        CP_ASYNC16(b + GTILE_B + sm0,   gBh + k0);
        CP_ASYNC16(b + GTILE_B + sm1,   gBh + R64 + k0);
        CP_ASYNC16(b + 2*GTILE_B + sm0, gBl + k0);
        CP_ASYNC16(b + 2*GTILE_B + sm1, gBl + R64 + k0);
        CP_COMMIT();
    };

    issue(0); issue(1);
    #pragma unroll 1
    for (int ch = 0; ch < 32; ch++) {
        CP_WAIT1();
        __syncthreads();
        if (ch + 2 < 32) issue(ch + 2);
        else             CP_COMMIT();
        uint32_t base = sbase + (ch % 3) * GBUF_B;
        #pragma unroll
        for (int k16 = 0; k16 < 2; k16++) {
            int kk = k16 << 4;
            uint32_t af[4][4], bh[4][2], bl[4][2];
            #pragma unroll
            for (int mt = 0; mt < 4; mt++) {
                uint32_t off = gswz(warpM + (mt << 4) + a_row, kk + a_kof) * 2;
                ldsm_x4(af[mt][0], af[mt][1], af[mt][2], af[mt][3], base + off);
            }
            #pragma unroll
            for (int np = 0; np < 2; np++) {
                uint32_t off = gswz(warpN + (np << 4) + b_nof + b_i, kk + b_kof) * 2;
                ldsm_x4(bh[2*np][0], bh[2*np][1], bh[2*np+1][0], bh[2*np+1][1],
                        base + GTILE_B + off);
                ldsm_x4(bl[2*np][0], bl[2*np][1], bl[2*np+1][0], bl[2*np+1][1],
                        base + 2*GTILE_B + off);
            }
            #pragma unroll
            for (int mt = 0; mt < 4; mt++)
                #pragma unroll
                for (int nt = 0; nt < 4; nt++) {
                    mma_f16(c[mt][nt], af[mt][0], af[mt][1], af[mt][2], af[mt][3],
                            bh[nt][0], bh[nt][1]);
                    mma_f16(c[mt][nt], af[mt][0], af[mt][1], af[mt][2], af[mt][3],
                            bl[nt][0], bl[nt][1]);
                }
        }
    }

    // ------------------- Epilogue -------------------
    int quad = lane >> 2, qi = lane & 3;
    const float LG10000 = 13.2877123795494f;

    #pragma unroll
    for (int nt = 0; nt < 4; nt++) {
        int col = n0 + warpN + (nt << 3) + (qi << 1);
        float b0 = bias[col], b1 = bias[col + 1];
        if (MODE == 1) {
            #pragma unroll
            for (int mt = 0; mt < 4; mt++) {
                int r0m = m0 + warpM + (mt << 4) + quad;
                *(float2*)&out[(size_t)r0m * HIDDEN + col] =
                    make_float2(c[mt][nt][0] + b0, c[mt][nt][1] + b1);
                *(float2*)&out[(size_t)(r0m + 8) * HIDDEN + col] =
                    make_float2(c[mt][nt][2] + b0, c[mt][nt][3] + b1);
            }
        } else {
            int which = col >> 10;
            int h = (col >> 6) & 15;
            int d = col & 63;
            size_t hb = (size_t)h * SEQ * HD;
            if (which == 2) {
                #pragma unroll
                for (int mt = 0; mt < 4; mt++) {
                    int r0m = m0 + warpM + (mt << 4) + quad;
                    #pragma unroll
                    for (int rr = 0; rr < 2; rr++) {
                        int m = r0m + (rr << 3);
                        int bb = m >> 11, t = m & 2047;
                        size_t base = ((size_t)bb * NH) * SEQ * HD + hb + (size_t)t * HD + d;
                        uint32_t h32, l32;
                        split16(c[mt][nt][2*rr] + b0, c[mt][nt][2*rr+1] + b1, h32, l32);
                        *(uint32_t*)&g_vh[base] = h32;
                        *(uint32_t*)&g_vl[base] = l32;
                    }
                }
            } else {
                int p = d >> 1;
                float invf = exp2f(-((float)p * (1.0f / 32.0f)) * LG10000);
                #pragma unroll
                for (int mt = 0; mt < 4; mt++) {
                    int r0m = m0 + warpM + (mt << 4) + quad;
                    #pragma unroll
                    for (int rr = 0; rr < 2; rr++) {
                        int m = r0m + (rr << 3);
                        int bb = m >> 11, t = m & 2047;
                        float s, cc;
                        sincosf((float)t * invf, &s, &cc);
                        float x1 = c[mt][nt][2*rr] + b0;
                        float x2 = c[mt][nt][2*rr+1] + b1;
                        float r1 = x1 * cc - x2 * s;
                        float r2 = x1 * s + x2 * cc;
                        size_t base = ((size_t)bb * NH) * SEQ * HD + hb + (size_t)t * HD + d;
                        if (which == 0) {
                            *(uint32_t*)&g_qs[base] = pack16(r1 * 0.125f, r2 * 0.125f);
                        } else {
                            uint32_t h32, l32;
                            split16(r1, r2, h32, l32);
                            *(uint32_t*)&g_kh[base] = h32;
                            *(uint32_t*)&g_kl[base] = l32;
                        }
                    }
                }
            }
        }
    }
}

// ===========================================================================
// fp16 flash attention: Q single (pre-scaled), K split, P single, V split.
// 128 q-rows/CTA (8 warps x 16), 64-key tiles, 3-stage cp.async ring.
// Per-buf: Kh,Kl,Vh,Vl tiles 8KB each = 32KB.
// ===========================================================================
#define ATILE_B 8192
#define ABUF_B  32768
#define ATTN_SMEM (3 * ABUF_B)   // 98304

__device__ __forceinline__ uint32_t aswz(int r, int c) {
    int seg = (c >> 3) ^ (r & 7);
    return (uint32_t)((r << 6) + (seg << 3) + (c & 7));
}

__global__ void __launch_bounds__(256, 2) attn_kernel()
{
    extern __shared__ char smemc[];
    const uint32_t sbase = smem_to_u32(smemc);

    int tid = threadIdx.x;
    int lane = tid & 31;
    int w = tid >> 5;
    int quad = lane >> 2, qi = lane & 3;
    int qt = gridDim.x - 1 - blockIdx.x;    // heavy tiles first
    int bh = blockIdx.y;
    size_t bh_base = (size_t)bh * SEQ * HD;

    // ---- Stage Q single (128x64 fp16 = 16KB) into buf region 0 ----
    #pragma unroll
    for (int i = 0; i < 4; i++) {
        int cidx = tid + (i << 8);               // 0..1023
        int r = cidx >> 3;
        int sg = (cidx & 7) << 3;
        uint4 v = *(const uint4*)&g_qs[bh_base + (size_t)(qt * 128 + r) * HD + sg];
        *(uint4*)(smemc + aswz(r, sg) * 2) = v;
    }
    __syncthreads();

    // ---- Q fragments ----
    uint32_t qf[4][4];
    {
        int arow = (w << 4) + (lane & 15);
        int akof = (lane >> 4) << 3;
        #pragma unroll
        for (int kk = 0; kk < 4; kk++) {
            uint32_t off = aswz(arow, (kk << 4) + akof) * 2;
            ldsm_x4(qf[kk][0], qf[kk][1], qf[kk][2], qf[kk][3], sbase + off);
        }
    }
    __syncthreads();   // Q extracted; buffers free

    // ---- K/V staging: per thread 4 tiles x rows {r0, r0+32} x one seg ----
    int r0 = tid >> 3, s8 = (tid & 7) << 3;
    uint32_t asm0 = aswz(r0, s8) * 2;
    uint32_t asm1 = aswz(r0 + 32, s8) * 2;
    const __half* gKh = g_kh + bh_base + (size_t)r0 * HD + s8;
    const __half* gKl = g_kl + bh_base + (size_t)r0 * HD + s8;
    const __half* gVh = g_vh + bh_base + (size_t)r0 * HD + s8;
    const __half* gVl = g_vl + bh_base + (size_t)r0 * HD + s8;
    const size_t R32 = (size_t)32 * HD;

    auto issue = [&](int kt) {
        uint32_t b = sbase + (kt % 3) * ABUF_B;
        size_t k0 = (size_t)kt << 12;
        CP_ASYNC16(b + asm0,             gKh + k0);
        CP_ASYNC16(b + asm1,             gKh + k0 + R32);
        CP_ASYNC16(b + ATILE_B + asm0,   gKl + k0);
        CP_ASYNC16(b + ATILE_B + asm1,   gKl + k0 + R32);
        CP_ASYNC16(b + 2*ATILE_B + asm0, gVh + k0);
        CP_ASYNC16(b + 2*ATILE_B + asm1, gVh + k0 + R32);
        CP_ASYNC16(b + 3*ATILE_B + asm0, gVl + k0);
        CP_ASYNC16(b + 3*ATILE_B + asm1, gVl + k0 + R32);
        CP_COMMIT();
    };

    float o[8][4];
    #pragma unroll
    for (int nt = 0; nt < 8; nt++)
        #pragma unroll
        for (int r = 0; r < 4; r++) o[nt][r] = 0.f;
    float m0 = -1e30f, m1 = -1e30f, l0 = 0.f, l1 = 0.f;
    int rowA = qt * 128 + (w << 4) + quad;
    int rowB = rowA + 8;
    int wmaxrow = qt * 128 + (w << 4) + 15;

    int b_g = lane >> 3, b_i = lane & 7;
    int b_nof = (b_g >> 1) << 3;
    int b_kof = (b_g & 1) << 3;
    int v_row = lane & 15;
    int v_cof = (lane >> 4) << 3;

    int ktmax = 2 * qt + 1;
    issue(0); issue(1);
    #pragma unroll 1
    for (int kt = 0; kt <= ktmax; kt++) {
        CP_WAIT1();
        __syncthreads();
        if (kt + 2 <= ktmax) issue(kt + 2);
        else                 CP_COMMIT();

        if (kt * 64 <= wmaxrow) {
            uint32_t base = sbase + (kt % 3) * ABUF_B;
            const uint32_t KH = base, KL = base + ATILE_B;
            const uint32_t VH = base + 2*ATILE_B, VL = base + 3*ATILE_B;

            // ---- S = Q K^T ----
            float s[8][4];
            #pragma unroll
            for (int nt = 0; nt < 8; nt++)
                #pragma unroll
                for (int r = 0; r < 4; r++) s[nt][r] = 0.f;
            #pragma unroll
            for (int kk = 0; kk < 4; kk++) {
                #pragma unroll
                for (int np = 0; np < 4; np++) {
                    uint32_t off = aswz((np << 4) + b_nof + b_i, (kk << 4) + b_kof) * 2;
                    uint32_t kb0, kb1, kb2, kb3, kc0, kc1, kc2, kc3;
                    ldsm_x4(kb0, kb1, kb2, kb3, KH + off);
                    ldsm_x4(kc0, kc1, kc2, kc3, KL + off);
                    mma_f16(s[2*np],   qf[kk][0], qf[kk][1], qf[kk][2], qf[kk][3], kb0, kb1);
                    mma_f16(s[2*np],   qf[kk][0], qf[kk][1], qf[kk][2], qf[kk][3], kc0, kc1);
                    mma_f16(s[2*np+1], qf[kk][0], qf[kk][1], qf[kk][2], qf[kk][3], kb2, kb3);
                    mma_f16(s[2*np+1], qf[kk][0], qf[kk][1], qf[kk][2], qf[kk][3], kc2, kc3);
                }
            }

            // ---- causal mask (boundary tiles only) ----
            if (kt >= 2 * qt) {
                #pragma unroll
                for (int nt = 0; nt < 8; nt++) {
                    int c0 = kt * 64 + (nt << 3) + (qi << 1);
                    if (c0     > rowA) s[nt][0] = -1e9f;
                    if (c0 + 1 > rowA) s[nt][1] = -1e9f;
                    if (c0     > rowB) s[nt][2] = -1e9f;
                    if (c0 + 1 > rowB) s[nt][3] = -1e9f;
                }
            }

            // ---- online softmax ----
            float mx0 = -1e30f, mx1 = -1e30f;
            #pragma unroll
            for (int nt = 0; nt < 8; nt++) {
                mx0 = fmaxf(mx0, fmaxf(s[nt][0], s[nt][1]));
                mx1 = fmaxf(mx1, fmaxf(s[nt][2], s[nt][3]));
            }
            mx0 = fmaxf(mx0, __shfl_xor_sync(0xffffffffu, mx0, 1));
            mx0 = fmaxf(mx0, __shfl_xor_sync(0xffffffffu, mx0, 2));
            mx1 = fmaxf(mx1, __shfl_xor_sync(0xffffffffu, mx1, 1));
            mx1 = fmaxf(mx1, __shfl_xor_sync(0xffffffffu, mx1, 2));
            float mn0 = fmaxf(m0, mx0), mn1 = fmaxf(m1, mx1);
            float a0 = __expf(m0 - mn0), a1 = __expf(m1 - mn1);
            float rs0 = 0.f, rs1 = 0.f;
            #pragma unroll
            for (int nt = 0; nt < 8; nt++) {
                s[nt][0] = __expf(s[nt][0] - mn0);
                s[nt][1] = __expf(s[nt][1] - mn0);
                s[nt][2] = __expf(s[nt][2] - mn1);
                s[nt][3] = __expf(s[nt][3] - mn1);
                rs0 += s[nt][0] + s[nt][1];
                rs1 += s[nt][2] + s[nt][3];
            }
            rs0 += __shfl_xor_sync(0xffffffffu, rs0, 1);
            rs0 += __shfl_xor_sync(0xffffffffu, rs0, 2);
            rs1 += __shfl_xor_sync(0xffffffffu, rs1, 1);
            rs1 += __shfl_xor_sync(0xffffffffu, rs1, 2);
            l0 = l0 * a0 + rs0;  l1 = l1 * a1 + rs1;
            m0 = mn0;  m1 = mn1;
            #pragma unroll
            for (int nt = 0; nt < 8; nt++) {
                o[nt][0] *= a0; o[nt][1] *= a0;
                o[nt][2] *= a1; o[nt][3] *= a1;
            }

            // ---- O += P V (P rounded to single fp16) ----
            #pragma unroll
            for (int j = 0; j < 4; j++) {
                uint32_t pa[4];
                pa[0] = pack16(s[2*j][0],   s[2*j][1]);
                pa[1] = pack16(s[2*j][2],   s[2*j][3]);
                pa[2] = pack16(s[2*j+1][0], s[2*j+1][1]);
                pa[3] = pack16(s[2*j+1][2], s[2*j+1][3]);
                #pragma unroll
                for (int np = 0; np < 4; np++) {
                    uint32_t off = aswz((j << 4) + v_row, (np << 4) + v_cof) * 2;
                    uint32_t vb0, vb1, vb2, vb3, vc0, vc1, vc2, vc3;
                    ldsm_x4_t(vb0, vb1, vb2, vb3, VH + off);
                    ldsm_x4_t(vc0, vc1, vc2, vc3, VL + off);
                    mma_f16(o[2*np],   pa[0], pa[1], pa[2], pa[3], vb0, vb1);
                    mma_f16(o[2*np],   pa[0], pa[1], pa[2], pa[3], vc0, vc1);
                    mma_f16(o[2*np+1], pa[0], pa[1], pa[2], pa[3], vb2, vb3);
                    mma_f16(o[2*np+1], pa[0], pa[1], pa[2], pa[3], vc2, vc3);
                }
            }
        }
        __syncthreads();
    }

    // ---- epilogue: normalize, round to fp16 [B,T,H*D] ----
    float i0 = 1.0f / l0, i1 = 1.0f / l1;
    int b = bh >> 4, h = bh & 15;
    size_t obaseA = ((size_t)b * SEQ + rowA) * HIDDEN + h * HD;
    size_t obaseB = ((size_t)b * SEQ + rowB) * HIDDEN + h * HD;
    #pragma unroll
    for (int nt = 0; nt < 8; nt++) {
        int col = (nt << 3) + (qi << 1);
        *(uint32_t*)&g_atts[obaseA + col] = pack16(o[nt][0] * i0, o[nt][1] * i0);
        *(uint32_t*)&g_atts[obaseB + col] = pack16(o[nt][2] * i1, o[nt][3] * i1);
    }
}

// ---------------------------------------------------------------------------
extern "C" void kernel_launch(void* const* d_in, const int* in_sizes, int n_in,
                              void* d_out, int out_size)
{
    const float* x    = (const float*)d_in[0];
    // d_in[1] = mask (bool) — pure causal, unused
    const float* Wqkv = (const float*)d_in[2];
    const float* bqkv = (const float*)d_in[3];
    const float* Wout = (const float*)d_in[4];
    const float* bout = (const float*)d_in[5];
    float* out = (float*)d_out;

    void *xs, *wqh, *wql, *woh, *wol;
    cudaGetSymbolAddress(&xs,  g_xs);
    cudaGetSymbolAddress(&wqh, g_wqh); cudaGetSymbolAddress(&wql, g_wql);
    cudaGetSymbolAddress(&woh, g_woh); cudaGetSymbolAddress(&wol, g_wol);

    cudaFuncSetAttribute(gemm_tc_kernel<0>, cudaFuncAttributeMaxDynamicSharedMemorySize, GEMM_SMEM);
    cudaFuncSetAttribute(gemm_tc_kernel<1>, cudaFuncAttributeMaxDynamicSharedMemorySize, GEMM_SMEM);
    cudaFuncSetAttribute(attn_kernel, cudaFuncAttributeMaxDynamicSharedMemorySize, ATTN_SMEM);

    round_x_kernel<<<(BT*HIDDEN/4 + 255)/256, 256>>>((const float4*)x, (uint2*)xs, BT*HIDDEN/4);
    split_w_kernel<<<(3*HIDDEN*HIDDEN/4 + 255)/256, 256>>>((const float4*)Wqkv,
        (uint2*)wqh, (uint2*)wql, 3*HIDDEN*HIDDEN/4);
    split_w_kernel<<<(HIDDEN*HIDDEN/4 + 255)/256, 256>>>((const float4*)Wout,
        (uint2*)woh, (uint2*)wol, HIDDEN*HIDDEN/4);

    // QKV + bias + RoPE -> q single / k,v splits
    gemm_tc_kernel<0><<<dim3(BT/128, 3*HIDDEN/128), 256, GEMM_SMEM>>>(bqkv, nullptr);

    // fp16 flash attention -> att single
    attn_kernel<<<dim3(SEQ/128, BATCH*NH), 256, ATTN_SMEM>>>();

    // Out projection -> fp32 out
    gemm_tc_kernel<1><<<dim3(BT/128, HIDDEN/128), 256, GEMM_SMEM>>>(bout, out);
}

// round 7
// speedup vs baseline: 5.4488x; 1.1991x over previous
#include <cuda_runtime.h>
#include <cuda_fp16.h>
#include <math.h>
#include <stdint.h>

#define HIDDEN 1024
#define NH 16
#define HD 64
#define BATCH 2
#define SEQ 2048
#define BT (BATCH*SEQ)   // 4096

// ---------------- fp16 scratch (device globals) ----------------
__device__ __half g_xs[BT*HIDDEN];                              // x rounded
__device__ __half g_wqh[3*HIDDEN*HIDDEN], g_wql[3*HIDDEN*HIDDEN];
__device__ __half g_woh[HIDDEN*HIDDEN],   g_wol[HIDDEN*HIDDEN];
__device__ __half g_qs[BT*HIDDEN];                              // q rounded, pre-scaled 1/8
__device__ __half g_ks[BT*HIDDEN];                              // k rounded
__device__ __half g_vs[BT*HIDDEN];                              // v rounded
__device__ __half g_atts[BT*HIDDEN];                            // attn out rounded

// ===========================================================================
// Primitives
// ===========================================================================
__device__ __forceinline__ uint32_t smem_to_u32(const void* smem_ptr) {
    uint32_t addr;
    asm("{ .reg .u64 tmp; cvta.to.shared.u64 tmp, %1; cvt.u32.u64 %0, tmp; }"
        : "=r"(addr) : "l"(smem_ptr));
    return addr;
}
__device__ __forceinline__ void ldsm_x4(uint32_t& r0, uint32_t& r1,
                                        uint32_t& r2, uint32_t& r3, uint32_t addr) {
    asm volatile("ldmatrix.sync.aligned.m8n8.x4.shared.b16 {%0,%1,%2,%3}, [%4];"
                 : "=r"(r0), "=r"(r1), "=r"(r2), "=r"(r3) : "r"(addr));
}
__device__ __forceinline__ void ldsm_x4_t(uint32_t& r0, uint32_t& r1,
                                          uint32_t& r2, uint32_t& r3, uint32_t addr) {
    asm volatile("ldmatrix.sync.aligned.m8n8.x4.trans.shared.b16 {%0,%1,%2,%3}, [%4];"
                 : "=r"(r0), "=r"(r1), "=r"(r2), "=r"(r3) : "r"(addr));
}
__device__ __forceinline__ void mma_f16(float* c,
                                        uint32_t a0, uint32_t a1, uint32_t a2, uint32_t a3,
                                        uint32_t b0, uint32_t b1) {
    asm volatile(
        "mma.sync.aligned.m16n8k16.row.col.f32.f16.f16.f32 "
        "{%0,%1,%2,%3}, {%4,%5,%6,%7}, {%8,%9}, {%0,%1,%2,%3};"
        : "+f"(c[0]), "+f"(c[1]), "+f"(c[2]), "+f"(c[3])
        : "r"(a0), "r"(a1), "r"(a2), "r"(a3), "r"(b0), "r"(b1));
}
__device__ __forceinline__ uint32_t pack16(float x1, float x2) {
    __half2 h = __floats2half2_rn(x1, x2);
    return *reinterpret_cast<uint32_t*>(&h);
}
__device__ __forceinline__ void split16(float x1, float x2, uint32_t& h, uint32_t& l) {
    __half2 hh = __floats2half2_rn(x1, x2);
    float2 hf = __half22float2(hh);
    __half2 ll = __floats2half2_rn(x1 - hf.x, x2 - hf.y);
    h = *reinterpret_cast<uint32_t*>(&hh);
    l = *reinterpret_cast<uint32_t*>(&ll);
}

#define CP_ASYNC16(sm, gp) \
    asm volatile("cp.async.cg.shared.global [%0], [%1], 16;" :: "r"(sm), "l"(gp))
#define CP_COMMIT() asm volatile("cp.async.commit_group;" ::: "memory")
#define CP_WAIT1() asm volatile("cp.async.wait_group 1;" ::: "memory")

// ===========================================================================
// Prep kernels
// ===========================================================================
__global__ void __launch_bounds__(256) split_w_kernel(
    const float4* __restrict__ src, uint2* __restrict__ h, uint2* __restrict__ l, int n4)
{
    int i = blockIdx.x * blockDim.x + threadIdx.x;
    if (i < n4) {
        float4 v = src[i];
        uint32_t h01, l01, h23, l23;
        split16(v.x, v.y, h01, l01);
        split16(v.z, v.w, h23, l23);
        h[i] = make_uint2(h01, h23);
        l[i] = make_uint2(l01, l23);
    }
}
__global__ void __launch_bounds__(256) round_x_kernel(
    const float4* __restrict__ src, uint2* __restrict__ s, int n4)
{
    int i = blockIdx.x * blockDim.x + threadIdx.x;
    if (i < n4) {
        float4 v = src[i];
        s[i] = make_uint2(pack16(v.x, v.y), pack16(v.z, v.w));
    }
}

// ===========================================================================
// HMMA GEMM: C[4096, N] = A[4096,1024] @ (Bh+Bl)[N,1024]^T, A single fp16.
// CTA 128x128, 8 warps (2Mx4N), K-chunks of 32, 3-stage cp.async ring.
// MODE 0: bias+RoPE -> q/k/v singles. MODE 1: bias -> fp32 out.
// ===========================================================================
#define GTILE_B 8192
#define GBUF_B  24576
#define GEMM_SMEM (3 * GBUF_B)   // 73728

__device__ __forceinline__ uint32_t gswz(int r, int c) {
    int seg = (c >> 3) ^ ((r >> 1) & 3);
    return (uint32_t)((r << 5) + (seg << 3) + (c & 7));
}

template<int MODE>
__global__ void __launch_bounds__(256, 2) gemm_tc_kernel(
    const float* __restrict__ bias, float* __restrict__ out)
{
    extern __shared__ char smem[];
    const uint32_t sbase = smem_to_u32(smem);

    const __half* As = (MODE == 0) ? g_xs  : g_atts;
    const __half* Bh = (MODE == 0) ? g_wqh : g_woh;
    const __half* Bl = (MODE == 0) ? g_wql : g_wol;

    int tid = threadIdx.x, lane = tid & 31, wid = tid >> 5;
    int warpM = (wid & 1) << 6, warpN = (wid >> 1) << 5;
    int m0 = blockIdx.x * 128, n0 = blockIdx.y * 128;

    int r0 = tid >> 2, s8 = (tid & 3) << 3;
    uint32_t sm0 = gswz(r0, s8) * 2;
    uint32_t sm1 = gswz(r0 + 64, s8) * 2;
    const __half* gAs = As + (size_t)(m0 + r0) * HIDDEN + s8;
    const __half* gBh = Bh + (size_t)(n0 + r0) * HIDDEN + s8;
    const __half* gBl = Bl + (size_t)(n0 + r0) * HIDDEN + s8;
    const size_t R64 = (size_t)64 * HIDDEN;

    int a_row = lane & 15, a_kof = (lane >> 4) << 3;
    int b_g = lane >> 3, b_i = lane & 7;
    int b_nof = (b_g >> 1) << 3, b_kof = (b_g & 1) << 3;

    float c[4][4][4];
    #pragma unroll
    for (int mt = 0; mt < 4; mt++)
        #pragma unroll
        for (int nt = 0; nt < 4; nt++)
            #pragma unroll
            for (int r = 0; r < 4; r++) c[mt][nt][r] = 0.f;

    auto issue = [&](int ch) {
        uint32_t b = sbase + (ch % 3) * GBUF_B;
        int k0 = ch << 5;
        CP_ASYNC16(b + sm0,             gAs + k0);
        CP_ASYNC16(b + sm1,             gAs + R64 + k0);
        CP_ASYNC16(b + GTILE_B + sm0,   gBh + k0);
        CP_ASYNC16(b + GTILE_B + sm1,   gBh + R64 + k0);
        CP_ASYNC16(b + 2*GTILE_B + sm0, gBl + k0);
        CP_ASYNC16(b + 2*GTILE_B + sm1, gBl + R64 + k0);
        CP_COMMIT();
    };

    issue(0); issue(1);
    #pragma unroll 1
    for (int ch = 0; ch < 32; ch++) {
        CP_WAIT1();
        __syncthreads();
        if (ch + 2 < 32) issue(ch + 2);
        else             CP_COMMIT();
        uint32_t base = sbase + (ch % 3) * GBUF_B;
        #pragma unroll
        for (int k16 = 0; k16 < 2; k16++) {
            int kk = k16 << 4;
            uint32_t af[4][4], bh[4][2], bl[4][2];
            #pragma unroll
            for (int mt = 0; mt < 4; mt++) {
                uint32_t off = gswz(warpM + (mt << 4) + a_row, kk + a_kof) * 2;
                ldsm_x4(af[mt][0], af[mt][1], af[mt][2], af[mt][3], base + off);
            }
            #pragma unroll
            for (int np = 0; np < 2; np++) {
                uint32_t off = gswz(warpN + (np << 4) + b_nof + b_i, kk + b_kof) * 2;
                ldsm_x4(bh[2*np][0], bh[2*np][1], bh[2*np+1][0], bh[2*np+1][1],
                        base + GTILE_B + off);
                ldsm_x4(bl[2*np][0], bl[2*np][1], bl[2*np+1][0], bl[2*np+1][1],
                        base + 2*GTILE_B + off);
            }
            #pragma unroll
            for (int mt = 0; mt < 4; mt++)
                #pragma unroll
                for (int nt = 0; nt < 4; nt++) {
                    mma_f16(c[mt][nt], af[mt][0], af[mt][1], af[mt][2], af[mt][3],
                            bh[nt][0], bh[nt][1]);
                    mma_f16(c[mt][nt], af[mt][0], af[mt][1], af[mt][2], af[mt][3],
                            bl[nt][0], bl[nt][1]);
                }
        }
    }

    // ------------------- Epilogue -------------------
    int quad = lane >> 2, qi = lane & 3;
    const float LG10000 = 13.2877123795494f;

    #pragma unroll
    for (int nt = 0; nt < 4; nt++) {
        int col = n0 + warpN + (nt << 3) + (qi << 1);
        float b0 = bias[col], b1 = bias[col + 1];
        if (MODE == 1) {
            #pragma unroll
            for (int mt = 0; mt < 4; mt++) {
                int r0m = m0 + warpM + (mt << 4) + quad;
                *(float2*)&out[(size_t)r0m * HIDDEN + col] =
                    make_float2(c[mt][nt][0] + b0, c[mt][nt][1] + b1);
                *(float2*)&out[(size_t)(r0m + 8) * HIDDEN + col] =
                    make_float2(c[mt][nt][2] + b0, c[mt][nt][3] + b1);
            }
        } else {
            int which = col >> 10;
            int h = (col >> 6) & 15;
            int d = col & 63;
            size_t hb = (size_t)h * SEQ * HD;
            if (which == 2) {
                #pragma unroll
                for (int mt = 0; mt < 4; mt++) {
                    int r0m = m0 + warpM + (mt << 4) + quad;
                    #pragma unroll
                    for (int rr = 0; rr < 2; rr++) {
                        int m = r0m + (rr << 3);
                        int bb = m >> 11, t = m & 2047;
                        size_t base = ((size_t)bb * NH) * SEQ * HD + hb + (size_t)t * HD + d;
                        *(uint32_t*)&g_vs[base] =
                            pack16(c[mt][nt][2*rr] + b0, c[mt][nt][2*rr+1] + b1);
                    }
                }
            } else {
                __half* dst = which ? g_ks : g_qs;
                float qscale = which ? 1.0f : 0.125f;
                int p = d >> 1;
                float invf = exp2f(-((float)p * (1.0f / 32.0f)) * LG10000);
                #pragma unroll
                for (int mt = 0; mt < 4; mt++) {
                    int r0m = m0 + warpM + (mt << 4) + quad;
                    #pragma unroll
                    for (int rr = 0; rr < 2; rr++) {
                        int m = r0m + (rr << 3);
                        int bb = m >> 11, t = m & 2047;
                        float s, cc;
                        sincosf((float)t * invf, &s, &cc);
                        float x1 = c[mt][nt][2*rr] + b0;
                        float x2 = c[mt][nt][2*rr+1] + b1;
                        size_t base = ((size_t)bb * NH) * SEQ * HD + hb + (size_t)t * HD + d;
                        *(uint32_t*)&dst[base] = pack16((x1 * cc - x2 * s) * qscale,
                                                        (x1 * s + x2 * cc) * qscale);
                    }
                }
            }
        }
    }
}

// ===========================================================================
// fp16 flash attention, all-single operands (Q pre-scaled, K, P, V fp16).
// 128 q-rows/CTA (8 warps x 16), 64-key tiles, 3-stage cp.async ring.
// Per-buf: K tile 8KB + V tile 8KB = 16KB.
// ===========================================================================
#define ATILE_B 8192
#define ABUF_B  16384
#define ATTN_SMEM (3 * ABUF_B)   // 49152

__device__ __forceinline__ uint32_t aswz(int r, int c) {
    int seg = (c >> 3) ^ (r & 7);
    return (uint32_t)((r << 6) + (seg << 3) + (c & 7));
}

__global__ void __launch_bounds__(256, 2) attn_kernel()
{
    extern __shared__ char smemc[];
    const uint32_t sbase = smem_to_u32(smemc);

    int tid = threadIdx.x;
    int lane = tid & 31;
    int w = tid >> 5;
    int quad = lane >> 2, qi = lane & 3;
    int qt = gridDim.x - 1 - blockIdx.x;    // heavy tiles first
    int bh = blockIdx.y;
    size_t bh_base = (size_t)bh * SEQ * HD;

    // ---- Stage Q single (128x64 fp16 = 16KB) into buf region 0 ----
    #pragma unroll
    for (int i = 0; i < 4; i++) {
        int cidx = tid + (i << 8);               // 0..1023
        int r = cidx >> 3;
        int sg = (cidx & 7) << 3;
        uint4 v = *(const uint4*)&g_qs[bh_base + (size_t)(qt * 128 + r) * HD + sg];
        *(uint4*)(smemc + aswz(r, sg) * 2) = v;
    }
    __syncthreads();

    // ---- Q fragments ----
    uint32_t qf[4][4];
    {
        int arow = (w << 4) + (lane & 15);
        int akof = (lane >> 4) << 3;
        #pragma unroll
        for (int kk = 0; kk < 4; kk++) {
            uint32_t off = aswz(arow, (kk << 4) + akof) * 2;
            ldsm_x4(qf[kk][0], qf[kk][1], qf[kk][2], qf[kk][3], sbase + off);
        }
    }
    __syncthreads();   // Q extracted; buffers free

    // ---- K/V staging: per thread rows {r0, r0+32} x one 16B seg ----
    int r0 = tid >> 3, s8 = (tid & 7) << 3;
    uint32_t asm0 = aswz(r0, s8) * 2;
    uint32_t asm1 = aswz(r0 + 32, s8) * 2;
    const __half* gK = g_ks + bh_base + (size_t)r0 * HD + s8;
    const __half* gV = g_vs + bh_base + (size_t)r0 * HD + s8;
    const size_t R32 = (size_t)32 * HD;

    auto issue = [&](int kt) {
        uint32_t b = sbase + (kt % 3) * ABUF_B;
        size_t k0 = (size_t)kt << 12;
        CP_ASYNC16(b + asm0,           gK + k0);
        CP_ASYNC16(b + asm1,           gK + k0 + R32);
        CP_ASYNC16(b + ATILE_B + asm0, gV + k0);
        CP_ASYNC16(b + ATILE_B + asm1, gV + k0 + R32);
        CP_COMMIT();
    };

    float o[8][4];
    #pragma unroll
    for (int nt = 0; nt < 8; nt++)
        #pragma unroll
        for (int r = 0; r < 4; r++) o[nt][r] = 0.f;
    float m0 = -1e30f, m1 = -1e30f, l0 = 0.f, l1 = 0.f;
    int rowA = qt * 128 + (w << 4) + quad;
    int rowB = rowA + 8;
    int wmaxrow = qt * 128 + (w << 4) + 15;

    int b_g = lane >> 3, b_i = lane & 7;
    int b_nof = (b_g >> 1) << 3;
    int b_kof = (b_g & 1) << 3;
    int v_row = lane & 15;
    int v_cof = (lane >> 4) << 3;

    int ktmax = 2 * qt + 1;
    issue(0); issue(1);
    #pragma unroll 1
    for (int kt = 0; kt <= ktmax; kt++) {
        CP_WAIT1();
        __syncthreads();
        if (kt + 2 <= ktmax) issue(kt + 2);
        else                 CP_COMMIT();

        if (kt * 64 <= wmaxrow) {
            uint32_t base = sbase + (kt % 3) * ABUF_B;
            const uint32_t KH = base, VH = base + ATILE_B;

            // ---- S = Q K^T ----
            float s[8][4];
            #pragma unroll
            for (int nt = 0; nt < 8; nt++)
                #pragma unroll
                for (int r = 0; r < 4; r++) s[nt][r] = 0.f;
            #pragma unroll
            for (int kk = 0; kk < 4; kk++) {
                #pragma unroll
                for (int np = 0; np < 4; np++) {
                    uint32_t off = aswz((np << 4) + b_nof + b_i, (kk << 4) + b_kof) * 2;
                    uint32_t kb0, kb1, kb2, kb3;
                    ldsm_x4(kb0, kb1, kb2, kb3, KH + off);
                    mma_f16(s[2*np],   qf[kk][0], qf[kk][1], qf[kk][2], qf[kk][3], kb0, kb1);
                    mma_f16(s[2*np+1], qf[kk][0], qf[kk][1], qf[kk][2], qf[kk][3], kb2, kb3);
                }
            }

            // ---- causal mask (boundary tiles only) ----
            if (kt >= 2 * qt) {
                #pragma unroll
                for (int nt = 0; nt < 8; nt++) {
                    int c0 = kt * 64 + (nt << 3) + (qi << 1);
                    if (c0     > rowA) s[nt][0] = -1e9f;
                    if (c0 + 1 > rowA) s[nt][1] = -1e9f;
                    if (c0     > rowB) s[nt][2] = -1e9f;
                    if (c0 + 1 > rowB) s[nt][3] = -1e9f;
                }
            }

            // ---- online softmax ----
            float mx0 = -1e30f, mx1 = -1e30f;
            #pragma unroll
            for (int nt = 0; nt < 8; nt++) {
                mx0 = fmaxf(mx0, fmaxf(s[nt][0], s[nt][1]));
                mx1 = fmaxf(mx1, fmaxf(s[nt][2], s[nt][3]));
            }
            mx0 = fmaxf(mx0, __shfl_xor_sync(0xffffffffu, mx0, 1));
            mx0 = fmaxf(mx0, __shfl_xor_sync(0xffffffffu, mx0, 2));
            mx1 = fmaxf(mx1, __shfl_xor_sync(0xffffffffu, mx1, 1));
            mx1 = fmaxf(mx1, __shfl_xor_sync(0xffffffffu, mx1, 2));
            float mn0 = fmaxf(m0, mx0), mn1 = fmaxf(m1, mx1);
            float a0 = __expf(m0 - mn0), a1 = __expf(m1 - mn1);
            float rs0 = 0.f, rs1 = 0.f;
            #pragma unroll
            for (int nt = 0; nt < 8; nt++) {
                s[nt][0] = __expf(s[nt][0] - mn0);
                s[nt][1] = __expf(s[nt][1] - mn0);
                s[nt][2] = __expf(s[nt][2] - mn1);
                s[nt][3] = __expf(s[nt][3] - mn1);
                rs0 += s[nt][0] + s[nt][1];
                rs1 += s[nt][2] + s[nt][3];
            }
            rs0 += __shfl_xor_sync(0xffffffffu, rs0, 1);
            rs0 += __shfl_xor_sync(0xffffffffu, rs0, 2);
            rs1 += __shfl_xor_sync(0xffffffffu, rs1, 1);
            rs1 += __shfl_xor_sync(0xffffffffu, rs1, 2);
            l0 = l0 * a0 + rs0;  l1 = l1 * a1 + rs1;
            m0 = mn0;  m1 = mn1;
            #pragma unroll
            for (int nt = 0; nt < 8; nt++) {
                o[nt][0] *= a0; o[nt][1] *= a0;
                o[nt][2] *= a1; o[nt][3] *= a1;
            }

            // ---- O += P V (P rounded to fp16) ----
            #pragma unroll
            for (int j = 0; j < 4; j++) {
                uint32_t pa[4];
                pa[0] = pack16(s[2*j][0],   s[2*j][1]);
                pa[1] = pack16(s[2*j][2],   s[2*j][3]);
                pa[2] = pack16(s[2*j+1][0], s[2*j+1][1]);
                pa[3] = pack16(s[2*j+1][2], s[2*j+1][3]);
                #pragma unroll
                for (int np = 0; np < 4; np++) {
                    uint32_t off = aswz((j << 4) + v_row, (np << 4) + v_cof) * 2;
                    uint32_t vb0, vb1, vb2, vb3;
                    ldsm_x4_t(vb0, vb1, vb2, vb3, VH + off);
                    mma_f16(o[2*np],   pa[0], pa[1], pa[2], pa[3], vb0, vb1);
                    mma_f16(o[2*np+1], pa[0], pa[1], pa[2], pa[3], vb2, vb3);
                }
            }
        }
        __syncthreads();
    }

    // ---- epilogue: normalize, round to fp16 [B,T,H*D] ----
    float i0 = 1.0f / l0, i1 = 1.0f / l1;
    int b = bh >> 4, h = bh & 15;
    size_t obaseA = ((size_t)b * SEQ + rowA) * HIDDEN + h * HD;
    size_t obaseB = ((size_t)b * SEQ + rowB) * HIDDEN + h * HD;
    #pragma unroll
    for (int nt = 0; nt < 8; nt++) {
        int col = (nt << 3) + (qi << 1);
        *(uint32_t*)&g_atts[obaseA + col] = pack16(o[nt][0] * i0, o[nt][1] * i0);
        *(uint32_t*)&g_atts[obaseB + col] = pack16(o[nt][2] * i1, o[nt][3] * i1);
    }
}

// ---------------------------------------------------------------------------
extern "C" void kernel_launch(void* const* d_in, const int* in_sizes, int n_in,
                              void* d_out, int out_size)
{
    const float* x    = (const float*)d_in[0];
    // d_in[1] = mask (bool) — pure causal, unused
    const float* Wqkv = (const float*)d_in[2];
    const float* bqkv = (const float*)d_in[3];
    const float* Wout = (const float*)d_in[4];
    const float* bout = (const float*)d_in[5];
    float* out = (float*)d_out;

    void *xs, *wqh, *wql, *woh, *wol;
    cudaGetSymbolAddress(&xs,  g_xs);
    cudaGetSymbolAddress(&wqh, g_wqh); cudaGetSymbolAddress(&wql, g_wql);
    cudaGetSymbolAddress(&woh, g_woh); cudaGetSymbolAddress(&wol, g_wol);

    cudaFuncSetAttribute(gemm_tc_kernel<0>, cudaFuncAttributeMaxDynamicSharedMemorySize, GEMM_SMEM);
    cudaFuncSetAttribute(gemm_tc_kernel<1>, cudaFuncAttributeMaxDynamicSharedMemorySize, GEMM_SMEM);
    cudaFuncSetAttribute(attn_kernel, cudaFuncAttributeMaxDynamicSharedMemorySize, ATTN_SMEM);

    round_x_kernel<<<(BT*HIDDEN/4 + 255)/256, 256>>>((const float4*)x, (uint2*)xs, BT*HIDDEN/4);
    split_w_kernel<<<(3*HIDDEN*HIDDEN/4 + 255)/256, 256>>>((const float4*)Wqkv,
        (uint2*)wqh, (uint2*)wql, 3*HIDDEN*HIDDEN/4);
    split_w_kernel<<<(HIDDEN*HIDDEN/4 + 255)/256, 256>>>((const float4*)Wout,
        (uint2*)woh, (uint2*)wol, HIDDEN*HIDDEN/4);

    // QKV + bias + RoPE -> q/k/v singles
    gemm_tc_kernel<0><<<dim3(BT/128, 3*HIDDEN/128), 256, GEMM_SMEM>>>(bqkv, nullptr);

    // fp16 flash attention -> att single
    attn_kernel<<<dim3(SEQ/128, BATCH*NH), 256, ATTN_SMEM>>>();

    // Out projection -> fp32 out
    gemm_tc_kernel<1><<<dim3(BT/128, HIDDEN/128), 256, GEMM_SMEM>>>(bout, out);
}